// round 2
// baseline (speedup 1.0000x reference)
#include <cuda_runtime.h>
#include <math.h>

#define DIMV   1024
#define HEADS  16
#define DH     64
#define BATCH  4
#define SEQ    1024
#define BH     (BATCH*HEADS)
#define MROWS  (BATCH*SEQ)     // 4096

// ---------------- device scratch (no allocations allowed) ----------------
__device__ float g_Qr[BH*SEQ*DH];
__device__ float g_Qi[BH*SEQ*DH];
__device__ float g_Kr[BH*SEQ*DH];
__device__ float g_Ki[BH*SEQ*DH];
__device__ float g_Vr[BH*SEQ*DH];
__device__ float g_Vi[BH*SEQ*DH];
__device__ float g_Or[BATCH*SEQ*DIMV];
__device__ float g_Oi[BATCH*SEQ*DIMV];

// =================== complex GEMM:  C = A @ W^T + bias ===================
// A: [4096,1024] row-major (Ar,Ai), W: [1024,1024] row-major (so W^T => NT GEMM)
// mode 0/1/2 : A = x, C = Q/K/V written in head layout [bh][n][dh]
// mode 3     : A = g_O, C = outR/outI (flat [B,N,D]) = final output planes
__global__ void __launch_bounds__(256, 2) cgemm_kernel(
    const float* __restrict__ xr, const float* __restrict__ xi,
    const float* __restrict__ Wr, const float* __restrict__ Wi,
    const float* __restrict__ biasR, const float* __restrict__ biasI,
    float* __restrict__ outR, float* __restrict__ outI, int mode)
{
    __shared__ float Asr[16][128];
    __shared__ float Asi[16][128];
    __shared__ float Bsr[16][64];
    __shared__ float Bsi[16][64];

    const float* Ar = (mode == 3) ? g_Or : xr;
    const float* Ai = (mode == 3) ? g_Oi : xi;
    float* Cr;
    float* Ci;
    if      (mode == 0) { Cr = g_Qr; Ci = g_Qi; }
    else if (mode == 1) { Cr = g_Kr; Ci = g_Ki; }
    else if (mode == 2) { Cr = g_Vr; Ci = g_Vi; }
    else                { Cr = outR; Ci = outI; }

    const int tid = threadIdx.x;
    const int tx = tid & 15;        // n direction (16 * TN=4 = 64)
    const int ty = tid >> 4;        // m direction (16 * TM=8 = 128)
    const int rowBase = blockIdx.y * 128;
    const int colBase = blockIdx.x * 64;

    float cr[8][4];
    float cim[8][4];
#pragma unroll
    for (int i = 0; i < 8; i++)
#pragma unroll
        for (int j = 0; j < 4; j++) { cr[i][j] = 0.f; cim[i][j] = 0.f; }

    const int lrow = tid >> 2;           // 0..63
    const int lkq  = (tid & 3) << 2;     // 0,4,8,12

    for (int k0 = 0; k0 < 1024; k0 += 16) {
        // ---- stage A tile (128x16), transposed into smem ----
#pragma unroll
        for (int s = 0; s < 2; s++) {
            const int row = lrow + s * 64;
            const size_t off = (size_t)(rowBase + row) * 1024 + k0 + lkq;
            float4 a = *(const float4*)(Ar + off);
            Asr[lkq + 0][row] = a.x; Asr[lkq + 1][row] = a.y;
            Asr[lkq + 2][row] = a.z; Asr[lkq + 3][row] = a.w;
            float4 b = *(const float4*)(Ai + off);
            Asi[lkq + 0][row] = b.x; Asi[lkq + 1][row] = b.y;
            Asi[lkq + 2][row] = b.z; Asi[lkq + 3][row] = b.w;
        }
        // ---- stage W tile (64x16), transposed ----
        {
            const size_t off = (size_t)(colBase + lrow) * 1024 + k0 + lkq;
            float4 a = *(const float4*)(Wr + off);
            Bsr[lkq + 0][lrow] = a.x; Bsr[lkq + 1][lrow] = a.y;
            Bsr[lkq + 2][lrow] = a.z; Bsr[lkq + 3][lrow] = a.w;
            float4 b = *(const float4*)(Wi + off);
            Bsi[lkq + 0][lrow] = b.x; Bsi[lkq + 1][lrow] = b.y;
            Bsi[lkq + 2][lrow] = b.z; Bsi[lkq + 3][lrow] = b.w;
        }
        __syncthreads();

#pragma unroll
        for (int kk = 0; kk < 16; kk++) {
            float ar[8], ai[8], brv[4], biv[4];
            *(float4*)(&ar[0]) = *(const float4*)(&Asr[kk][ty * 8]);
            *(float4*)(&ar[4]) = *(const float4*)(&Asr[kk][ty * 8 + 4]);
            *(float4*)(&ai[0]) = *(const float4*)(&Asi[kk][ty * 8]);
            *(float4*)(&ai[4]) = *(const float4*)(&Asi[kk][ty * 8 + 4]);
            *(float4*)(&brv[0]) = *(const float4*)(&Bsr[kk][tx * 4]);
            *(float4*)(&biv[0]) = *(const float4*)(&Bsi[kk][tx * 4]);
#pragma unroll
            for (int i = 0; i < 8; i++) {
#pragma unroll
                for (int j = 0; j < 4; j++) {
                    cr[i][j]  = fmaf(ar[i],  brv[j], cr[i][j]);
                    cr[i][j]  = fmaf(-ai[i], biv[j], cr[i][j]);
                    cim[i][j] = fmaf(ar[i],  biv[j], cim[i][j]);
                    cim[i][j] = fmaf(ai[i],  brv[j], cim[i][j]);
                }
            }
        }
        __syncthreads();
    }

    // ---- epilogue ----
#pragma unroll
    for (int i = 0; i < 8; i++) {
        const int m = rowBase + ty * 8 + i;
#pragma unroll
        for (int j = 0; j < 4; j++) {
            const int c = colBase + tx * 4 + j;
            const float vr = cr[i][j]  + biasR[c];
            const float vi = cim[i][j] + biasI[c];
            size_t dst;
            if (mode != 3) {
                const int b = m >> 10, n = m & 1023;
                const int h = c >> 6,  d = c & 63;
                dst = ((size_t)(b * HEADS + h) * SEQ + n) * DH + d;
            } else {
                dst = (size_t)m * 1024 + c;
            }
            Cr[dst] = vr;
            Ci[dst] = vi;
        }
    }
}

// =================== attention kernel ===================
// grid: (SEQ/64, BH). One block = 64 queries of one (b,h).
// P = exp(sqrt(sim_r^2 + sim_i^2) / 8)  (logits >= 0 and bounded ~7, so no
// max-subtraction needed; identical math to reference softmax).
#define AP 68   // padded row stride (floats), multiple of 4, avoids bank conflicts

__global__ void __launch_bounds__(256) attn_kernel()
{
    extern __shared__ float sm[];
    float* Qr = sm;
    float* Qi = Qr + 64 * AP;
    float* Kr = Qi + 64 * AP;
    float* Ki = Kr + 64 * AP;
    float* Vr = Ki + 64 * AP;
    float* Vi = Vr + 64 * AP;
    float* P  = Vi + 64 * AP;
    float* rowsum = P + 64 * AP;

    const int tid = threadIdx.x;
    const int tq = tid >> 4;   // 0..15 -> query rows tq*4..tq*4+3
    const int tk = tid & 15;   // 0..15 -> key cols tk+16j (P) / dh cols tk*4.. (PV)
    const int bh = blockIdx.y;
    const int n0 = blockIdx.x * 64;
    const size_t qbase = ((size_t)bh * SEQ + n0) * DH;

    // load Q tile (64x64 r+i)
#pragma unroll
    for (int s = 0; s < 4; s++) {
        const int slot = tid + s * 256;
        const int row = slot >> 4;
        const int d4 = (slot & 15) << 2;
        *(float4*)(&Qr[row * AP + d4]) = *(const float4*)(&g_Qr[qbase + row * 64 + d4]);
        *(float4*)(&Qi[row * AP + d4]) = *(const float4*)(&g_Qi[qbase + row * 64 + d4]);
    }

    float accR[4][4] = {};
    float accI[4][4] = {};
    float rs[4] = {0.f, 0.f, 0.f, 0.f};

    for (int kt = 0; kt < 16; kt++) {
        __syncthreads();   // previous-iter P/V consumers done (also orders Q load on kt=0... actually load below)
        const size_t kbase = ((size_t)bh * SEQ + kt * 64) * DH;
#pragma unroll
        for (int s = 0; s < 4; s++) {
            const int slot = tid + s * 256;
            const int row = slot >> 4;
            const int d4 = (slot & 15) << 2;
            *(float4*)(&Kr[row * AP + d4]) = *(const float4*)(&g_Kr[kbase + row * 64 + d4]);
            *(float4*)(&Ki[row * AP + d4]) = *(const float4*)(&g_Ki[kbase + row * 64 + d4]);
            *(float4*)(&Vr[row * AP + d4]) = *(const float4*)(&g_Vr[kbase + row * 64 + d4]);
            *(float4*)(&Vi[row * AP + d4]) = *(const float4*)(&g_Vi[kbase + row * 64 + d4]);
        }
        __syncthreads();

        // ---- sim (4q x 4k per thread) ----
        float sr[4][4] = {};
        float si[4][4] = {};
#pragma unroll 8
        for (int d = 0; d < 64; d++) {
            float qr[4], qi[4], kr[4], ki[4];
#pragma unroll
            for (int i = 0; i < 4; i++) {
                qr[i] = Qr[(tq * 4 + i) * AP + d];
                qi[i] = Qi[(tq * 4 + i) * AP + d];
            }
#pragma unroll
            for (int j = 0; j < 4; j++) {
                const int k = tk + 16 * j;
                kr[j] = Kr[k * AP + d];
                ki[j] = Ki[k * AP + d];
            }
#pragma unroll
            for (int i = 0; i < 4; i++) {
#pragma unroll
                for (int j = 0; j < 4; j++) {
                    sr[i][j] = fmaf(qr[i],  kr[j], sr[i][j]);
                    sr[i][j] = fmaf(qi[i],  ki[j], sr[i][j]);
                    si[i][j] = fmaf(qi[i],  kr[j], si[i][j]);
                    si[i][j] = fmaf(-qr[i], ki[j], si[i][j]);
                }
            }
        }
        // ---- magnitude -> exp -> stage P ----
#pragma unroll
        for (int i = 0; i < 4; i++) {
            float rsum = 0.f;
#pragma unroll
            for (int j = 0; j < 4; j++) {
                const float mag = sqrtf(sr[i][j] * sr[i][j] + si[i][j] * si[i][j]) * 0.125f;
                const float p = __expf(mag);
                P[(tq * 4 + i) * AP + tk + 16 * j] = p;
                rsum += p;
            }
            rs[i] += rsum;
        }
        __syncthreads();

        // ---- O += P @ V (4q x 4d per thread) ----
#pragma unroll 4
        for (int k = 0; k < 64; k++) {
            float p[4];
#pragma unroll
            for (int i = 0; i < 4; i++) p[i] = P[(tq * 4 + i) * AP + k];
            const float4 vr4 = *(const float4*)(&Vr[k * AP + tk * 4]);
            const float4 vi4 = *(const float4*)(&Vi[k * AP + tk * 4]);
            const float vrv[4] = {vr4.x, vr4.y, vr4.z, vr4.w};
            const float viv[4] = {vi4.x, vi4.y, vi4.z, vi4.w};
#pragma unroll
            for (int i = 0; i < 4; i++) {
#pragma unroll
                for (int j = 0; j < 4; j++) {
                    accR[i][j] = fmaf(p[i], vrv[j], accR[i][j]);
                    accI[i][j] = fmaf(p[i], viv[j], accI[i][j]);
                }
            }
        }
    }
    __syncthreads();

    // ---- rowsum reduction across the 16 tk threads (reuse P as scratch) ----
#pragma unroll
    for (int i = 0; i < 4; i++) P[(tq * 4 + i) * AP + tk] = rs[i];
    __syncthreads();
    if (tid < 64) {
        float s = 0.f;
#pragma unroll
        for (int t = 0; t < 16; t++) s += P[tid * AP + t];
        rowsum[tid] = s;
    }
    __syncthreads();

    // ---- normalize + store to [B,N,DIM] layout ----
    const int b = bh >> 4, h = bh & 15;
#pragma unroll
    for (int i = 0; i < 4; i++) {
        const int q = tq * 4 + i;
        const float inv = 1.0f / rowsum[q];
        const size_t obase = ((size_t)b * SEQ + (n0 + q)) * DIMV + h * DH + tk * 4;
#pragma unroll
        for (int j = 0; j < 4; j++) {
            g_Or[obase + j] = accR[i][j] * inv;
            g_Oi[obase + j] = accI[i][j] * inv;
        }
    }
}

// =================== launcher ===================
extern "C" void kernel_launch(void* const* d_in, const int* in_sizes, int n_in,
                              void* d_out, int out_size)
{
    const float* xr = (const float*)d_in[0];
    const float* xi = (const float*)d_in[1];
    const float* Wr = (const float*)d_in[2];
    const float* Wi = (const float*)d_in[3];
    const float* br = (const float*)d_in[4];
    const float* bi = (const float*)d_in[5];

    float* outR = (float*)d_out;
    float* outI = outR + (size_t)BATCH * SEQ * DIMV;   // [2,B,N,D] imag plane

    const int ATTN_SMEM = (7 * 64 * AP + 64) * (int)sizeof(float);  // ~122 KB
    cudaFuncSetAttribute(attn_kernel, cudaFuncAttributeMaxDynamicSharedMemorySize,
                         ATTN_SMEM);

    const dim3 ggrid(16, 32);   // N/64 x M/128
    const size_t WSTRIDE = (size_t)DIMV * DIMV;

    // Q, K, V projections
    cgemm_kernel<<<ggrid, 256>>>(xr, xi, Wr + 0 * WSTRIDE, Wi + 0 * WSTRIDE,
                                 br + 0 * DIMV, bi + 0 * DIMV, nullptr, nullptr, 0);
    cgemm_kernel<<<ggrid, 256>>>(xr, xi, Wr + 1 * WSTRIDE, Wi + 1 * WSTRIDE,
                                 br + 1 * DIMV, bi + 1 * DIMV, nullptr, nullptr, 1);
    cgemm_kernel<<<ggrid, 256>>>(xr, xi, Wr + 2 * WSTRIDE, Wi + 2 * WSTRIDE,
                                 br + 2 * DIMV, bi + 2 * DIMV, nullptr, nullptr, 2);

    // attention
    attn_kernel<<<dim3(SEQ / 64, BH), 256, ATTN_SMEM>>>();

    // output projection -> d_out
    cgemm_kernel<<<ggrid, 256>>>(nullptr, nullptr, Wr + 3 * WSTRIDE, Wi + 3 * WSTRIDE,
                                 br + 3 * DIMV, bi + 3 * DIMV, outR, outI, 3);
}

// round 4
// speedup vs baseline: 1.7559x; 1.7559x over previous
#include <cuda_runtime.h>
#include <cuda_bf16.h>
#include <math.h>
#include <stdint.h>

#define DIMV   1024
#define HEADS  16
#define DH     64
#define BATCH  4
#define SEQ    1024
#define BH     (BATCH*HEADS)
#define K_EFF  6144
#define KBYTES (K_EFF*2)

// ---------------- device scratch ----------------
__device__ float g_Qr[BH*SEQ*DH];
__device__ float g_Qi[BH*SEQ*DH];
__device__ float g_Kr[BH*SEQ*DH];
__device__ float g_Ki[BH*SEQ*DH];
__device__ float g_Vr[BH*SEQ*DH];
__device__ float g_Vi[BH*SEQ*DH];
__device__ float g_Or[BATCH*SEQ*DIMV];
__device__ float g_Oi[BATCH*SEQ*DIMV];
__device__ __nv_bfloat16 g_Acat[(size_t)8192*K_EFF];
__device__ __nv_bfloat16 g_Wcat[(size_t)4096*K_EFF];

// ---------------- ptx helpers (baseline sm_80-class only) ----------------
__device__ __forceinline__ uint32_t smem_u32(const void* p) {
    uint32_t a;
    asm("{ .reg .u64 t; cvta.to.shared.u64 t, %1; cvt.u32.u64 %0, t; }" : "=r"(a) : "l"(p));
    return a;
}
__device__ __forceinline__ void cp16(uint32_t dst, const void* src) {
    asm volatile("cp.async.cg.shared.global [%0], [%1], 16;" :: "r"(dst), "l"(src) : "memory");
}
__device__ __forceinline__ void cp_commit() { asm volatile("cp.async.commit_group;" ::: "memory"); }
template<int N> __device__ __forceinline__ void cp_wait() {
    asm volatile("cp.async.wait_group %0;" :: "n"(N) : "memory");
}
__device__ __forceinline__ void ldsm4(uint32_t* r, uint32_t addr) {
    asm volatile("ldmatrix.sync.aligned.m8n8.x4.shared.b16 {%0,%1,%2,%3}, [%4];"
                 : "=r"(r[0]), "=r"(r[1]), "=r"(r[2]), "=r"(r[3]) : "r"(addr));
}
__device__ __forceinline__ void mma16816(float* c, const uint32_t* a, uint32_t b0, uint32_t b1) {
    asm volatile(
        "mma.sync.aligned.m16n8k16.row.col.f32.bf16.bf16.f32 "
        "{%0,%1,%2,%3}, {%4,%5,%6,%7}, {%8,%9}, {%0,%1,%2,%3};"
        : "+f"(c[0]), "+f"(c[1]), "+f"(c[2]), "+f"(c[3])
        : "r"(a[0]), "r"(a[1]), "r"(a[2]), "r"(a[3]), "r"(b0), "r"(b1));
}

// ---------------- conversion kernels ----------------
__device__ __forceinline__ void bsplit(float x, __nv_bfloat16& h, __nv_bfloat16& l) {
    h = __float2bfloat16_rn(x);
    l = __float2bfloat16_rn(x - __bfloat162float(h));
}
__device__ __forceinline__ void st4b(__nv_bfloat16* p, const __nv_bfloat16* v) {
    ushort4 u;
    u.x = __bfloat16_as_ushort(v[0]); u.y = __bfloat16_as_ushort(v[1]);
    u.z = __bfloat16_as_ushort(v[2]); u.w = __bfloat16_as_ushort(v[3]);
    *(ushort4*)p = u;
}
__device__ __forceinline__ void st4bn(__nv_bfloat16* p, const __nv_bfloat16* v) {
    ushort4 u;
    u.x = __bfloat16_as_ushort(__hneg(v[0])); u.y = __bfloat16_as_ushort(__hneg(v[1]));
    u.z = __bfloat16_as_ushort(__hneg(v[2])); u.w = __bfloat16_as_ushort(__hneg(v[3]));
    *(ushort4*)p = u;
}

// A rows: real = [hr hr lr -hi -hi -li], imag = [hi hi li hr hr lr]
__global__ void conv_a_kernel(const float* __restrict__ ar_in,
                              const float* __restrict__ ai_in, int useO)
{
    const float* ar = useO ? g_Or : ar_in;
    const float* ai = useO ? g_Oi : ai_in;
    const int idx = blockIdx.x * 256 + threadIdx.x;
    const int row = idx >> 8;
    const int c = (idx & 255) << 2;
    const size_t src = (size_t)row * 1024 + c;
    const float4 vr = *(const float4*)(ar + src);
    const float4 vi = *(const float4*)(ai + src);
    const float fr[4] = {vr.x, vr.y, vr.z, vr.w};
    const float fi[4] = {vi.x, vi.y, vi.z, vi.w};
    __nv_bfloat16 hr[4], lr[4], hj[4], lj[4];
#pragma unroll
    for (int t = 0; t < 4; t++) { bsplit(fr[t], hr[t], lr[t]); bsplit(fi[t], hj[t], lj[t]); }
    __nv_bfloat16* Re = g_Acat + (size_t)row * K_EFF + c;
    __nv_bfloat16* Im = g_Acat + (size_t)(row + 4096) * K_EFF + c;
    st4b (Re + 0,    hr); st4b (Re + 1024, hr); st4b (Re + 2048, lr);
    st4bn(Re + 3072, hj); st4bn(Re + 4096, hj); st4bn(Re + 5120, lj);
    st4b (Im + 0,    hj); st4b (Im + 1024, hj); st4b (Im + 2048, lj);
    st4b (Im + 3072, hr); st4b (Im + 4096, hr); st4b (Im + 5120, lr);
}

// W rows: [hWr lWr hWr hWi lWi hWi]
__global__ void conv_w_kernel(const float* __restrict__ Wr, const float* __restrict__ Wi)
{
    const int idx = blockIdx.x * 256 + threadIdx.x;
    const int row = idx >> 8;
    const int c = (idx & 255) << 2;
    const size_t src = (size_t)row * 1024 + c;
    const float4 vr = *(const float4*)(Wr + src);
    const float4 vi = *(const float4*)(Wi + src);
    const float fr[4] = {vr.x, vr.y, vr.z, vr.w};
    const float fi[4] = {vi.x, vi.y, vi.z, vi.w};
    __nv_bfloat16 hr[4], lr[4], hj[4], lj[4];
#pragma unroll
    for (int t = 0; t < 4; t++) { bsplit(fr[t], hr[t], lr[t]); bsplit(fi[t], hj[t], lj[t]); }
    __nv_bfloat16* W = g_Wcat + (size_t)row * K_EFF + c;
    st4b(W + 0,    hr); st4b(W + 1024, lr); st4b(W + 2048, hr);
    st4b(W + 3072, hj); st4b(W + 4096, lj); st4b(W + 5120, hj);
}

// ---------------- mma.sync GEMM ----------------
#define BM 128
#define BN 128
#define BK 64
#define NITER (K_EFF/BK)      // 96
#define A_ST  16384           // 128 rows * 128B
#define ST_SZ 32768           // A + B per stage
#define SMEM_GEMM (3*ST_SZ)   // 98304

__device__ __forceinline__ void load_stage(uint32_t sbase, int s, int kt, int tid,
                                           const __nv_bfloat16* Ab, const __nv_bfloat16* Bb)
{
    const char* aSrc = (const char*)Ab + (size_t)kt * (BK * 2);
    const char* bSrc = (const char*)Bb + (size_t)kt * (BK * 2);
    const uint32_t aDst = sbase + s * ST_SZ;
    const uint32_t bDst = aDst + A_ST;
#pragma unroll
    for (int i = 0; i < 4; i++) {
        const int q = tid + i * 256;
        const int row = q >> 3, cc = q & 7;
        const uint32_t off = row * 128 + cc * 16;
        const uint32_t sw = off ^ ((off >> 3) & 0x70);
        cp16(aDst + sw, aSrc + (size_t)row * KBYTES + cc * 16);
        cp16(bDst + sw, bSrc + (size_t)row * KBYTES + cc * 16);
    }
}

__device__ __forceinline__ void epi_store(int mode, int gm, int gc,
                                          float v0, float v1,
                                          const float* biasR, const float* biasI,
                                          float* outR, float* outI)
{
    const int plane = gm >> 12;
    const int m = gm & 4095;
    const int b = m >> 10, n = m & 1023;
    const float* bias = plane ? biasI : biasR;
    float2 v;
    v.x = v0 + bias[gc];
    v.y = v1 + bias[gc + 1];
    float* base;
    size_t dst;
    if (mode == 0) {
        const int layer = gc >> 10;
        const int cw = gc & 1023;
        const int h = cw >> 6, d = cw & 63;
        if (layer == 0)      base = plane ? g_Qi : g_Qr;
        else if (layer == 1) base = plane ? g_Ki : g_Kr;
        else                 base = plane ? g_Vi : g_Vr;
        dst = ((size_t)(b * HEADS + h) * SEQ + n) * DH + d;
    } else {
        base = plane ? outI : outR;
        dst = (size_t)m * 1024 + gc;
    }
    *(float2*)(base + dst) = v;
}

__global__ void __launch_bounds__(256, 2) mma_gemm(
    const float* __restrict__ biasR, const float* __restrict__ biasI,
    float* __restrict__ outR, float* __restrict__ outI, int mode)
{
    extern __shared__ char smem[];
    const uint32_t sbase = smem_u32(smem);
    const int tid = threadIdx.x;
    const int lane = tid & 31;
    const int wid = tid >> 5;
    const int wm = wid & 3;      // warp rows: wm*32
    const int wn = wid >> 2;     // warp cols: wn*64

    const __nv_bfloat16* Ab = g_Acat + (size_t)blockIdx.y * BM * K_EFF;
    const __nv_bfloat16* Bb = g_Wcat + (mode ? (size_t)3072 * K_EFF : 0)
                                     + (size_t)blockIdx.x * BN * K_EFF;

    float acc[2][8][4];
#pragma unroll
    for (int mt = 0; mt < 2; mt++)
#pragma unroll
        for (int nt = 0; nt < 8; nt++)
#pragma unroll
            for (int r = 0; r < 4; r++) acc[mt][nt][r] = 0.f;

    load_stage(sbase, 0, 0, tid, Ab, Bb); cp_commit();
    load_stage(sbase, 1, 1, tid, Ab, Bb); cp_commit();

    const int lr_ = lane & 15;
    const int lc16 = (lane >> 4) * 16;

    for (int kt = 0; kt < NITER; kt++) {
        cp_wait<1>();
        __syncthreads();
        const int slot = kt % 3;
        const uint32_t aB = sbase + slot * ST_SZ;
        const uint32_t bB = aB + A_ST;
#pragma unroll
        for (int ks = 0; ks < 4; ks++) {
            const uint32_t cb = ks * 32 + lc16;
            uint32_t af[2][4], bf[4][4];
#pragma unroll
            for (int mt = 0; mt < 2; mt++) {
                const uint32_t off = (uint32_t)(wm * 32 + mt * 16 + lr_) * 128 + cb;
                ldsm4(af[mt], aB + (off ^ ((off >> 3) & 0x70)));
            }
#pragma unroll
            for (int pr = 0; pr < 4; pr++) {
                const uint32_t off = (uint32_t)(wn * 64 + pr * 16 + lr_) * 128 + cb;
                ldsm4(bf[pr], bB + (off ^ ((off >> 3) & 0x70)));
            }
#pragma unroll
            for (int mt = 0; mt < 2; mt++)
#pragma unroll
                for (int nt = 0; nt < 8; nt++)
                    mma16816(acc[mt][nt], af[mt],
                             bf[nt >> 1][nt & 1], bf[nt >> 1][(nt & 1) + 2]);
        }
        const int pk = kt + 2;
        if (pk < NITER) load_stage(sbase, pk % 3, pk, tid, Ab, Bb);
        cp_commit();
    }

    const int blockRow = blockIdx.y * BM;
    const int blockCol = blockIdx.x * BN;
#pragma unroll
    for (int mt = 0; mt < 2; mt++) {
        const int gr0 = blockRow + wm * 32 + mt * 16 + (lane >> 2);
#pragma unroll
        for (int nt = 0; nt < 8; nt++) {
            const int gc = blockCol + wn * 64 + nt * 8 + (lane & 3) * 2;
            epi_store(mode, gr0,     gc, acc[mt][nt][0], acc[mt][nt][1], biasR, biasI, outR, outI);
            epi_store(mode, gr0 + 8, gc, acc[mt][nt][2], acc[mt][nt][3], biasR, biasI, outR, outI);
        }
    }
}

// =================== attention kernel (unchanged, passing) ===================
#define AP 68

__global__ void __launch_bounds__(256) attn_kernel()
{
    extern __shared__ float sm[];
    float* Qr = sm;
    float* Qi = Qr + 64 * AP;
    float* Kr = Qi + 64 * AP;
    float* Ki = Kr + 64 * AP;
    float* Vr = Ki + 64 * AP;
    float* Vi = Vr + 64 * AP;
    float* P  = Vi + 64 * AP;
    float* rowsum = P + 64 * AP;

    const int tid = threadIdx.x;
    const int tq = tid >> 4;
    const int tk = tid & 15;
    const int bh = blockIdx.y;
    const int n0 = blockIdx.x * 64;
    const size_t qbase = ((size_t)bh * SEQ + n0) * DH;

#pragma unroll
    for (int s = 0; s < 4; s++) {
        const int slot = tid + s * 256;
        const int row = slot >> 4;
        const int d4 = (slot & 15) << 2;
        *(float4*)(&Qr[row * AP + d4]) = *(const float4*)(&g_Qr[qbase + row * 64 + d4]);
        *(float4*)(&Qi[row * AP + d4]) = *(const float4*)(&g_Qi[qbase + row * 64 + d4]);
    }

    float accR[4][4] = {};
    float accI[4][4] = {};
    float rs[4] = {0.f, 0.f, 0.f, 0.f};

    for (int kt = 0; kt < 16; kt++) {
        __syncthreads();
        const size_t kbase = ((size_t)bh * SEQ + kt * 64) * DH;
#pragma unroll
        for (int s = 0; s < 4; s++) {
            const int slot = tid + s * 256;
            const int row = slot >> 4;
            const int d4 = (slot & 15) << 2;
            *(float4*)(&Kr[row * AP + d4]) = *(const float4*)(&g_Kr[kbase + row * 64 + d4]);
            *(float4*)(&Ki[row * AP + d4]) = *(const float4*)(&g_Ki[kbase + row * 64 + d4]);
            *(float4*)(&Vr[row * AP + d4]) = *(const float4*)(&g_Vr[kbase + row * 64 + d4]);
            *(float4*)(&Vi[row * AP + d4]) = *(const float4*)(&g_Vi[kbase + row * 64 + d4]);
        }
        __syncthreads();

        float sr[4][4] = {};
        float si[4][4] = {};
#pragma unroll 8
        for (int d = 0; d < 64; d++) {
            float qr[4], qi[4], kr[4], ki[4];
#pragma unroll
            for (int i = 0; i < 4; i++) {
                qr[i] = Qr[(tq * 4 + i) * AP + d];
                qi[i] = Qi[(tq * 4 + i) * AP + d];
            }
#pragma unroll
            for (int j = 0; j < 4; j++) {
                const int k = tk + 16 * j;
                kr[j] = Kr[k * AP + d];
                ki[j] = Ki[k * AP + d];
            }
#pragma unroll
            for (int i = 0; i < 4; i++) {
#pragma unroll
                for (int j = 0; j < 4; j++) {
                    sr[i][j] = fmaf(qr[i],  kr[j], sr[i][j]);
                    sr[i][j] = fmaf(qi[i],  ki[j], sr[i][j]);
                    si[i][j] = fmaf(qi[i],  kr[j], si[i][j]);
                    si[i][j] = fmaf(-qr[i], ki[j], si[i][j]);
                }
            }
        }
#pragma unroll
        for (int i = 0; i < 4; i++) {
            float rsum = 0.f;
#pragma unroll
            for (int j = 0; j < 4; j++) {
                const float mag = sqrtf(sr[i][j] * sr[i][j] + si[i][j] * si[i][j]) * 0.125f;
                const float p = __expf(mag);
                P[(tq * 4 + i) * AP + tk + 16 * j] = p;
                rsum += p;
            }
            rs[i] += rsum;
        }
        __syncthreads();

#pragma unroll 4
        for (int k = 0; k < 64; k++) {
            float p[4];
#pragma unroll
            for (int i = 0; i < 4; i++) p[i] = P[(tq * 4 + i) * AP + k];
            const float4 vr4 = *(const float4*)(&Vr[k * AP + tk * 4]);
            const float4 vi4 = *(const float4*)(&Vi[k * AP + tk * 4]);
            const float vrv[4] = {vr4.x, vr4.y, vr4.z, vr4.w};
            const float viv[4] = {vi4.x, vi4.y, vi4.z, vi4.w};
#pragma unroll
            for (int i = 0; i < 4; i++) {
#pragma unroll
                for (int j = 0; j < 4; j++) {
                    accR[i][j] = fmaf(p[i], vrv[j], accR[i][j]);
                    accI[i][j] = fmaf(p[i], viv[j], accI[i][j]);
                }
            }
        }
    }
    __syncthreads();

#pragma unroll
    for (int i = 0; i < 4; i++) P[(tq * 4 + i) * AP + tk] = rs[i];
    __syncthreads();
    if (tid < 64) {
        float s = 0.f;
#pragma unroll
        for (int t = 0; t < 16; t++) s += P[tid * AP + t];
        rowsum[tid] = s;
    }
    __syncthreads();

    const int b = bh >> 4, h = bh & 15;
#pragma unroll
    for (int i = 0; i < 4; i++) {
        const int q = tq * 4 + i;
        const float inv = 1.0f / rowsum[q];
        const size_t obase = ((size_t)b * SEQ + (n0 + q)) * DIMV + h * DH + tk * 4;
#pragma unroll
        for (int j = 0; j < 4; j++) {
            g_Or[obase + j] = accR[i][j] * inv;
            g_Oi[obase + j] = accI[i][j] * inv;
        }
    }
}

// =================== launcher ===================
extern "C" void kernel_launch(void* const* d_in, const int* in_sizes, int n_in,
                              void* d_out, int out_size)
{
    const float* xr = (const float*)d_in[0];
    const float* xi = (const float*)d_in[1];
    const float* Wr = (const float*)d_in[2];
    const float* Wi = (const float*)d_in[3];
    const float* br = (const float*)d_in[4];
    const float* bi = (const float*)d_in[5];

    float* outR = (float*)d_out;
    float* outI = outR + (size_t)BATCH * SEQ * DIMV;

    const int ATTN_SMEM = (7 * 64 * AP + 64) * (int)sizeof(float);
    cudaFuncSetAttribute(attn_kernel, cudaFuncAttributeMaxDynamicSharedMemorySize, ATTN_SMEM);
    cudaFuncSetAttribute(mma_gemm, cudaFuncAttributeMaxDynamicSharedMemorySize, SMEM_GEMM);

    conv_a_kernel<<<4096, 256>>>(xr, xi, 0);
    conv_w_kernel<<<4096, 256>>>(Wr, Wi);

    // fused QKV projection: C[8192 x 3072]
    mma_gemm<<<dim3(3072 / BN, 8192 / BM), 256, SMEM_GEMM>>>(br, bi, nullptr, nullptr, 0);

    attn_kernel<<<dim3(SEQ / 64, BH), 256, ATTN_SMEM>>>();

    // rebuild A from attention output, then output projection -> d_out
    conv_a_kernel<<<4096, 256>>>(nullptr, nullptr, 1);
    mma_gemm<<<dim3(1024 / BN, 8192 / BM), 256, SMEM_GEMM>>>(br + 3 * DIMV, bi + 3 * DIMV,
                                                             outR, outI, 1);
}

// round 5
// speedup vs baseline: 2.4980x; 1.4227x over previous
#include <cuda_runtime.h>
#include <cuda_bf16.h>
#include <math.h>
#include <stdint.h>

#define DIMV   1024
#define HEADS  16
#define DH     64
#define BATCH  4
#define SEQ    1024
#define BH     (BATCH*HEADS)
#define K_EFF  6144
#define KBYTES (K_EFF*2)

// ---------------- device scratch ----------------
__device__ float g_Qr[BH*SEQ*DH];
__device__ float g_Qi[BH*SEQ*DH];
__device__ float g_Kr[BH*SEQ*DH];
__device__ float g_Ki[BH*SEQ*DH];
__device__ float g_Vr[BH*SEQ*DH];
__device__ float g_Vi[BH*SEQ*DH];
__device__ float g_Or[BATCH*SEQ*DIMV];
__device__ float g_Oi[BATCH*SEQ*DIMV];
__device__ __nv_bfloat16 g_Acat[(size_t)8192*K_EFF];
__device__ __nv_bfloat16 g_Wcat[(size_t)4096*K_EFF];
// attention packed operands
__device__ __nv_bfloat16 g_Qpack[(size_t)BH*SEQ*384];        // [bh][n][384]
__device__ __nv_bfloat16 g_Kpack[(size_t)BH*2*SEQ*384];      // [bh][variant][n][384]
__device__ __nv_bfloat16 g_Vpack[(size_t)BH*16*128*128];     // [bh][ktile][d(128)][vh|vl (128)]

// ---------------- ptx helpers ----------------
__device__ __forceinline__ uint32_t smem_u32(const void* p) {
    uint32_t a;
    asm("{ .reg .u64 t; cvta.to.shared.u64 t, %1; cvt.u32.u64 %0, t; }" : "=r"(a) : "l"(p));
    return a;
}
__device__ __forceinline__ void cp16(uint32_t dst, const void* src) {
    asm volatile("cp.async.cg.shared.global [%0], [%1], 16;" :: "r"(dst), "l"(src) : "memory");
}
__device__ __forceinline__ void cp_commit() { asm volatile("cp.async.commit_group;" ::: "memory"); }
template<int N> __device__ __forceinline__ void cp_wait() {
    asm volatile("cp.async.wait_group %0;" :: "n"(N) : "memory");
}
__device__ __forceinline__ void ldsm4(uint32_t* r, uint32_t addr) {
    asm volatile("ldmatrix.sync.aligned.m8n8.x4.shared.b16 {%0,%1,%2,%3}, [%4];"
                 : "=r"(r[0]), "=r"(r[1]), "=r"(r[2]), "=r"(r[3]) : "r"(addr));
}
__device__ __forceinline__ void mma16816(float* c, const uint32_t* a, uint32_t b0, uint32_t b1) {
    asm volatile(
        "mma.sync.aligned.m16n8k16.row.col.f32.bf16.bf16.f32 "
        "{%0,%1,%2,%3}, {%4,%5,%6,%7}, {%8,%9}, {%0,%1,%2,%3};"
        : "+f"(c[0]), "+f"(c[1]), "+f"(c[2]), "+f"(c[3])
        : "r"(a[0]), "r"(a[1]), "r"(a[2]), "r"(a[3]), "r"(b0), "r"(b1));
}
__device__ __forceinline__ uint32_t sw128(uint32_t off) { return off ^ ((off >> 3) & 0x70); }

// ---------------- split helpers ----------------
__device__ __forceinline__ void bsplit(float x, __nv_bfloat16& h, __nv_bfloat16& l) {
    h = __float2bfloat16_rn(x);
    l = __float2bfloat16_rn(x - __bfloat162float(h));
}
__device__ __forceinline__ void st4b(__nv_bfloat16* p, const __nv_bfloat16* v) {
    ushort4 u;
    u.x = __bfloat16_as_ushort(v[0]); u.y = __bfloat16_as_ushort(v[1]);
    u.z = __bfloat16_as_ushort(v[2]); u.w = __bfloat16_as_ushort(v[3]);
    *(ushort4*)p = u;
}
__device__ __forceinline__ void st4bn(__nv_bfloat16* p, const __nv_bfloat16* v) {
    ushort4 u;
    u.x = __bfloat16_as_ushort(__hneg(v[0])); u.y = __bfloat16_as_ushort(__hneg(v[1]));
    u.z = __bfloat16_as_ushort(__hneg(v[2])); u.w = __bfloat16_as_ushort(__hneg(v[3]));
    *(ushort4*)p = u;
}

// ---------------- conversion: GEMM operands ----------------
__global__ void conv_a_kernel(const float* __restrict__ ar_in,
                              const float* __restrict__ ai_in, int useO)
{
    const float* ar = useO ? g_Or : ar_in;
    const float* ai = useO ? g_Oi : ai_in;
    const int idx = blockIdx.x * 256 + threadIdx.x;
    const int row = idx >> 8;
    const int c = (idx & 255) << 2;
    const size_t src = (size_t)row * 1024 + c;
    const float4 vr = *(const float4*)(ar + src);
    const float4 vi = *(const float4*)(ai + src);
    const float fr[4] = {vr.x, vr.y, vr.z, vr.w};
    const float fi[4] = {vi.x, vi.y, vi.z, vi.w};
    __nv_bfloat16 hr[4], lr[4], hj[4], lj[4];
#pragma unroll
    for (int t = 0; t < 4; t++) { bsplit(fr[t], hr[t], lr[t]); bsplit(fi[t], hj[t], lj[t]); }
    __nv_bfloat16* Re = g_Acat + (size_t)row * K_EFF + c;
    __nv_bfloat16* Im = g_Acat + (size_t)(row + 4096) * K_EFF + c;
    st4b (Re + 0,    hr); st4b (Re + 1024, hr); st4b (Re + 2048, lr);
    st4bn(Re + 3072, hj); st4bn(Re + 4096, hj); st4bn(Re + 5120, lj);
    st4b (Im + 0,    hj); st4b (Im + 1024, hj); st4b (Im + 2048, lj);
    st4b (Im + 3072, hr); st4b (Im + 4096, hr); st4b (Im + 5120, lr);
}

__global__ void conv_w_kernel(const float* __restrict__ Wr, const float* __restrict__ Wi)
{
    const int idx = blockIdx.x * 256 + threadIdx.x;
    const int row = idx >> 8;
    const int c = (idx & 255) << 2;
    const size_t src = (size_t)row * 1024 + c;
    const float4 vr = *(const float4*)(Wr + src);
    const float4 vi = *(const float4*)(Wi + src);
    const float fr[4] = {vr.x, vr.y, vr.z, vr.w};
    const float fi[4] = {vi.x, vi.y, vi.z, vi.w};
    __nv_bfloat16 hr[4], lr[4], hj[4], lj[4];
#pragma unroll
    for (int t = 0; t < 4; t++) { bsplit(fr[t], hr[t], lr[t]); bsplit(fi[t], hj[t], lj[t]); }
    __nv_bfloat16* W = g_Wcat + (size_t)row * K_EFF + c;
    st4b(W + 0,    hr); st4b(W + 1024, lr); st4b(W + 2048, hr);
    st4b(W + 3072, hj); st4b(W + 4096, lj); st4b(W + 5120, hj);
}

// ---------------- conversion: attention packed operands ----------------
// Qpack row: [qrh qrh qrl qih qih qil]
// Kpack v0 : [krh krl krh kih kil kih]   (-> sim_r)
// Kpack v1 : [-kih -kil -kih krh krl krh] (-> sim_i)
__global__ void conv_qk_kernel()
{
    const int r = blockIdx.x * 16 + (threadIdx.x >> 4);
    const int d0 = (threadIdx.x & 15) << 2;
    const int bh = r >> 10, n = r & 1023;
    const size_t src = ((size_t)bh * SEQ + n) * DH + d0;
    const float4 q_r = *(const float4*)(g_Qr + src);
    const float4 q_i = *(const float4*)(g_Qi + src);
    const float4 k_r = *(const float4*)(g_Kr + src);
    const float4 k_i = *(const float4*)(g_Ki + src);
    const float fqr[4] = {q_r.x, q_r.y, q_r.z, q_r.w};
    const float fqi[4] = {q_i.x, q_i.y, q_i.z, q_i.w};
    const float fkr[4] = {k_r.x, k_r.y, k_r.z, k_r.w};
    const float fki[4] = {k_i.x, k_i.y, k_i.z, k_i.w};
    __nv_bfloat16 qrh[4], qrl[4], qih[4], qil[4], krh[4], krl[4], kih[4], kil[4];
#pragma unroll
    for (int t = 0; t < 4; t++) {
        bsplit(fqr[t], qrh[t], qrl[t]); bsplit(fqi[t], qih[t], qil[t]);
        bsplit(fkr[t], krh[t], krl[t]); bsplit(fki[t], kih[t], kil[t]);
    }
    __nv_bfloat16* Qp = g_Qpack + ((size_t)bh * SEQ + n) * 384 + d0;
    st4b(Qp + 0, qrh); st4b(Qp + 64, qrh); st4b(Qp + 128, qrl);
    st4b(Qp + 192, qih); st4b(Qp + 256, qih); st4b(Qp + 320, qil);
    __nv_bfloat16* K0 = g_Kpack + (((size_t)bh * 2 + 0) * SEQ + n) * 384 + d0;
    st4b(K0 + 0, krh); st4b(K0 + 64, krl); st4b(K0 + 128, krh);
    st4b(K0 + 192, kih); st4b(K0 + 256, kil); st4b(K0 + 320, kih);
    __nv_bfloat16* K1 = g_Kpack + (((size_t)bh * 2 + 1) * SEQ + n) * 384 + d0;
    st4bn(K1 + 0, kih); st4bn(K1 + 64, kil); st4bn(K1 + 128, kih);
    st4b (K1 + 192, krh); st4b(K1 + 256, krl); st4b(K1 + 320, krh);
}

// Vpack[bh][kt][d][j] = vh(key=kt*64+j, d),  [d][64+j] = vl.  d<64 -> Vr, d>=64 -> Vi
__global__ void conv_v_kernel()
{
    const int idx = blockIdx.x * 256 + threadIdx.x;
    const int bh = idx >> 14;
    const int local = idx & 16383;
    const int grp = local >> 6;        // key group of 4 (0..255)
    const int d = local & 63;
    const int key0 = grp * 4;
    const int kt = key0 >> 6, jloc = key0 & 63;
    __nv_bfloat16 vrh[4], vrl[4], vih[4], vil[4];
#pragma unroll
    for (int k = 0; k < 4; k++) {
        const size_t src = ((size_t)bh * SEQ + key0 + k) * DH + d;
        bsplit(g_Vr[src], vrh[k], vrl[k]);
        bsplit(g_Vi[src], vih[k], vil[k]);
    }
    __nv_bfloat16* base = g_Vpack + (((size_t)bh * 16 + kt) * 128) * 128;
    st4b(base + d * 128 + jloc, vrh);
    st4b(base + d * 128 + 64 + jloc, vrl);
    st4b(base + (64 + d) * 128 + jloc, vih);
    st4b(base + (64 + d) * 128 + 64 + jloc, vil);
}

// ---------------- mma.sync projection GEMM (unchanged from R3) ----------------
#define BM 128
#define BN 128
#define BK 64
#define NITER (K_EFF/BK)
#define A_ST  16384
#define ST_SZ 32768
#define SMEM_GEMM (3*ST_SZ)

__device__ __forceinline__ void load_stage(uint32_t sbase, int s, int kt, int tid,
                                           const __nv_bfloat16* Ab, const __nv_bfloat16* Bb)
{
    const char* aSrc = (const char*)Ab + (size_t)kt * (BK * 2);
    const char* bSrc = (const char*)Bb + (size_t)kt * (BK * 2);
    const uint32_t aDst = sbase + s * ST_SZ;
    const uint32_t bDst = aDst + A_ST;
#pragma unroll
    for (int i = 0; i < 4; i++) {
        const int q = tid + i * 256;
        const int row = q >> 3, cc = q & 7;
        const uint32_t sw = sw128(row * 128 + cc * 16);
        cp16(aDst + sw, aSrc + (size_t)row * KBYTES + cc * 16);
        cp16(bDst + sw, bSrc + (size_t)row * KBYTES + cc * 16);
    }
}

__device__ __forceinline__ void epi_store(int mode, int gm, int gc,
                                          float v0, float v1,
                                          const float* biasR, const float* biasI,
                                          float* outR, float* outI)
{
    const int plane = gm >> 12;
    const int m = gm & 4095;
    const int b = m >> 10, n = m & 1023;
    const float* bias = plane ? biasI : biasR;
    float2 v;
    v.x = v0 + bias[gc];
    v.y = v1 + bias[gc + 1];
    float* base;
    size_t dst;
    if (mode == 0) {
        const int layer = gc >> 10;
        const int cw = gc & 1023;
        const int h = cw >> 6, d = cw & 63;
        if (layer == 0)      base = plane ? g_Qi : g_Qr;
        else if (layer == 1) base = plane ? g_Ki : g_Kr;
        else                 base = plane ? g_Vi : g_Vr;
        dst = ((size_t)(b * HEADS + h) * SEQ + n) * DH + d;
    } else {
        base = plane ? outI : outR;
        dst = (size_t)m * 1024 + gc;
    }
    *(float2*)(base + dst) = v;
}

__global__ void __launch_bounds__(256, 2) mma_gemm(
    const float* __restrict__ biasR, const float* __restrict__ biasI,
    float* __restrict__ outR, float* __restrict__ outI, int mode)
{
    extern __shared__ char smem[];
    const uint32_t sbase = smem_u32(smem);
    const int tid = threadIdx.x;
    const int lane = tid & 31;
    const int wid = tid >> 5;
    const int wm = wid & 3;
    const int wn = wid >> 2;

    const __nv_bfloat16* Ab = g_Acat + (size_t)blockIdx.y * BM * K_EFF;
    const __nv_bfloat16* Bb = g_Wcat + (mode ? (size_t)3072 * K_EFF : 0)
                                     + (size_t)blockIdx.x * BN * K_EFF;

    float acc[2][8][4];
#pragma unroll
    for (int mt = 0; mt < 2; mt++)
#pragma unroll
        for (int nt = 0; nt < 8; nt++)
#pragma unroll
            for (int r = 0; r < 4; r++) acc[mt][nt][r] = 0.f;

    load_stage(sbase, 0, 0, tid, Ab, Bb); cp_commit();
    load_stage(sbase, 1, 1, tid, Ab, Bb); cp_commit();

    const int lr_ = lane & 15;
    const int lc16 = (lane >> 4) * 16;

    for (int kt = 0; kt < NITER; kt++) {
        cp_wait<1>();
        __syncthreads();
        const int slot = kt % 3;
        const uint32_t aB = sbase + slot * ST_SZ;
        const uint32_t bB = aB + A_ST;
#pragma unroll
        for (int ks = 0; ks < 4; ks++) {
            const uint32_t cb = ks * 32 + lc16;
            uint32_t af[2][4], bf[4][4];
#pragma unroll
            for (int mt = 0; mt < 2; mt++) {
                const uint32_t off = (uint32_t)(wm * 32 + mt * 16 + lr_) * 128 + cb;
                ldsm4(af[mt], aB + sw128(off));
            }
#pragma unroll
            for (int pr = 0; pr < 4; pr++) {
                const uint32_t off = (uint32_t)(wn * 64 + pr * 16 + lr_) * 128 + cb;
                ldsm4(bf[pr], bB + sw128(off));
            }
#pragma unroll
            for (int mt = 0; mt < 2; mt++)
#pragma unroll
                for (int nt = 0; nt < 8; nt++)
                    mma16816(acc[mt][nt], af[mt],
                             bf[nt >> 1][nt & 1], bf[nt >> 1][(nt & 1) + 2]);
        }
        const int pk = kt + 2;
        if (pk < NITER) load_stage(sbase, pk % 3, pk, tid, Ab, Bb);
        cp_commit();
    }

    const int blockRow = blockIdx.y * BM;
    const int blockCol = blockIdx.x * BN;
#pragma unroll
    for (int mt = 0; mt < 2; mt++) {
        const int gr0 = blockRow + wm * 32 + mt * 16 + (lane >> 2);
#pragma unroll
        for (int nt = 0; nt < 8; nt++) {
            const int gc = blockCol + wn * 64 + nt * 8 + (lane & 3) * 2;
            epi_store(mode, gr0,     gc, acc[mt][nt][0], acc[mt][nt][1], biasR, biasI, outR, outI);
            epi_store(mode, gr0 + 8, gc, acc[mt][nt][2], acc[mt][nt][3], biasR, biasI, outR, outI);
        }
    }
}

// =================== tensor-core attention ===================
// smem layout (bytes):
#define SQ_OFF 0
#define SK_OFF 98304            // 6*16KB Q
#define SP_OFF (SK_OFF + 3*16384)
#define SV_OFF (SP_OFF + 2*16384)
#define SRS_OFF (SV_OFF + 2*16384)
#define ATTN2_SMEM (SRS_OFF + 1024)

__global__ void __launch_bounds__(256, 1) attn2_kernel()
{
    extern __shared__ char sm[];
    const uint32_t sb = smem_u32(sm);
    const uint32_t sQ = sb + SQ_OFF;
    const uint32_t sK = sb + SK_OFF;
    const uint32_t sP = sb + SP_OFF;
    const uint32_t sV = sb + SV_OFF;
    float* sRS = (float*)(sm + SRS_OFF);

    const int tid = threadIdx.x;
    const int lane = tid & 31;
    const int wid = tid >> 5;
    const int wm = wid & 3;
    const int wn = wid >> 2;
    const int bh = blockIdx.y;
    const int n0 = blockIdx.x * 128;

    const char* Qg  = (const char*)(g_Qpack + ((size_t)bh * SEQ + n0) * 384);
    const char* Kg0 = (const char*)(g_Kpack + ((size_t)bh * 2 + 0) * SEQ * 384);
    const char* Kg1 = (const char*)(g_Kpack + ((size_t)bh * 2 + 1) * SEQ * 384);
    const char* Vg  = (const char*)(g_Vpack + (size_t)bh * 16 * 128 * 128);

    // ---- prologue: Q (one group), K0, K1 ----
#pragma unroll
    for (int c = 0; c < 6; c++) {
#pragma unroll
        for (int i = 0; i < 4; i++) {
            const int q = tid + i * 256;
            const int row = q >> 3, cc = q & 7;
            cp16(sQ + c * 16384 + sw128(row * 128 + cc * 16),
                 Qg + (size_t)row * 768 + c * 128 + cc * 16);
        }
    }
    cp_commit();

#define LOAD_K(cchunk, ktile, buf) do { \
    _Pragma("unroll") \
    for (int i = 0; i < 4; i++) { \
        const int q = tid + i * 256; \
        const int row = q >> 3, cc = q & 7; \
        const char* src = (row < 64) \
            ? Kg0 + (size_t)((ktile) * 64 + row) * 768 + (cchunk) * 128 + cc * 16 \
            : Kg1 + (size_t)((ktile) * 64 + row - 64) * 768 + (cchunk) * 128 + cc * 16; \
        cp16(sK + (buf) * 16384 + sw128(row * 128 + cc * 16), src); \
    } \
    cp_commit(); } while (0)

#define LOAD_V(half, ktile, buf) do { \
    _Pragma("unroll") \
    for (int i = 0; i < 4; i++) { \
        const int q = tid + i * 256; \
        const int row = q >> 3, cc = q & 7; \
        cp16(sV + (buf) * 16384 + sw128(row * 128 + cc * 16), \
             Vg + (size_t)(ktile) * 32768 + (size_t)row * 256 + (half) * 128 + cc * 16); \
    } \
    cp_commit(); } while (0)

    LOAD_K(0, 0, 0);
    LOAD_K(1, 0, 1);

    float accO[2][8][4];
#pragma unroll
    for (int mt = 0; mt < 2; mt++)
#pragma unroll
        for (int nt = 0; nt < 8; nt++)
#pragma unroll
            for (int e = 0; e < 4; e++) accO[mt][nt][e] = 0.f;
    float rs[2][2] = {{0.f, 0.f}, {0.f, 0.f}};

    const int lr_ = lane & 15;
    const int lc16 = (lane >> 4) * 16;

    for (int kt = 0; kt < 16; kt++) {
        float accS[2][8][4];
#pragma unroll
        for (int mt = 0; mt < 2; mt++)
#pragma unroll
            for (int nt = 0; nt < 8; nt++)
#pragma unroll
                for (int e = 0; e < 4; e++) accS[mt][nt][e] = 0.f;

        // ---- S GEMM over 6 k-chunks ----
#pragma unroll 1
        for (int c = 0; c < 6; c++) {
            if (c < 5) cp_wait<1>(); else cp_wait<0>();
            __syncthreads();
            const uint32_t aB = sQ + c * 16384;
            const uint32_t bB = sK + (c % 3) * 16384;
#pragma unroll
            for (int ks = 0; ks < 4; ks++) {
                const uint32_t cb = ks * 32 + lc16;
                uint32_t af[2][4], bf[4][4];
#pragma unroll
                for (int mt = 0; mt < 2; mt++) {
                    const uint32_t off = (uint32_t)(wm * 32 + mt * 16 + lr_) * 128 + cb;
                    ldsm4(af[mt], aB + sw128(off));
                }
#pragma unroll
                for (int pr = 0; pr < 4; pr++) {
                    const int rbase = (pr < 2) ? (wn * 32 + pr * 16)
                                               : (64 + wn * 32 + (pr - 2) * 16);
                    const uint32_t off = (uint32_t)(rbase + lr_) * 128 + cb;
                    ldsm4(bf[pr], bB + sw128(off));
                }
#pragma unroll
                for (int mt = 0; mt < 2; mt++)
#pragma unroll
                    for (int nt = 0; nt < 8; nt++)
                        mma16816(accS[mt][nt], af[mt],
                                 bf[nt >> 1][nt & 1], bf[nt >> 1][(nt & 1) + 2]);
            }
            if (c < 4) LOAD_K(c + 2, kt, (c + 2) % 3);
        }

        // ---- V loads for this tile ----
        LOAD_V(0, kt, 0);
        LOAD_V(1, kt, 1);

        // ---- softmax + pack P into smem (ph chunk0, pl chunk1) ----
#pragma unroll
        for (int mt = 0; mt < 2; mt++) {
#pragma unroll
            for (int nt = 0; nt < 4; nt++) {
                float p[4];
#pragma unroll
                for (int e = 0; e < 4; e++) {
                    const float srv = accS[mt][nt][e];
                    const float siv = accS[mt][nt + 4][e];
                    p[e] = __expf(sqrtf(srv * srv + siv * siv) * 0.125f);
                }
                rs[mt][0] += p[0] + p[1];
                rs[mt][1] += p[2] + p[3];
                const int keyb = (wn * 32 + nt * 8 + (lane & 3) * 2) * 2;  // byte col
                const int row0 = wm * 32 + mt * 16 + (lane >> 2);
#pragma unroll
                for (int half = 0; half < 2; half++) {
                    const float p0 = p[half * 2], p1 = p[half * 2 + 1];
                    const __nv_bfloat16 h0 = __float2bfloat16_rn(p0);
                    const __nv_bfloat16 h1 = __float2bfloat16_rn(p1);
                    const __nv_bfloat16 l0 = __float2bfloat16_rn(p0 - __bfloat162float(h0));
                    const __nv_bfloat16 l1 = __float2bfloat16_rn(p1 - __bfloat162float(h1));
                    const uint32_t off = (uint32_t)(row0 + half * 8) * 128 + keyb;
                    const uint32_t hpack = (uint32_t)__bfloat16_as_ushort(h0)
                                         | ((uint32_t)__bfloat16_as_ushort(h1) << 16);
                    const uint32_t lpack = (uint32_t)__bfloat16_as_ushort(l0)
                                         | ((uint32_t)__bfloat16_as_ushort(l1) << 16);
                    *(uint32_t*)(sm + SP_OFF + sw128(off)) = hpack;
                    *(uint32_t*)(sm + SP_OFF + 16384 + sw128(off)) = lpack;
                }
            }
        }

        // ---- PV: 3 chunks [ph*vh, ph*vl, pl*vh] ----
#pragma unroll 1
        for (int c = 0; c < 3; c++) {
            if (c == 0)      cp_wait<1>();
            else if (c == 1) { if (kt < 15) cp_wait<1>(); else cp_wait<0>(); }
            if (c == 0) __syncthreads();
            const uint32_t aB = sP + ((c == 2) ? 16384 : 0);
            const uint32_t bB = sV + ((c == 1) ? 16384 : 0);
#pragma unroll
            for (int ks = 0; ks < 4; ks++) {
                const uint32_t cb = ks * 32 + lc16;
                uint32_t af[2][4], bf[4][4];
#pragma unroll
                for (int mt = 0; mt < 2; mt++) {
                    const uint32_t off = (uint32_t)(wm * 32 + mt * 16 + lr_) * 128 + cb;
                    ldsm4(af[mt], aB + sw128(off));
                }
#pragma unroll
                for (int pr = 0; pr < 4; pr++) {
                    const uint32_t off = (uint32_t)(wn * 64 + pr * 16 + lr_) * 128 + cb;
                    ldsm4(bf[pr], bB + sw128(off));
                }
#pragma unroll
                for (int mt = 0; mt < 2; mt++)
#pragma unroll
                    for (int nt = 0; nt < 8; nt++)
                        mma16816(accO[mt][nt], af[mt],
                                 bf[nt >> 1][nt & 1], bf[nt >> 1][(nt & 1) + 2]);
            }
            if (kt < 15) {
                if (c == 0) LOAD_K(0, kt + 1, 0);
                else if (c == 1) LOAD_K(1, kt + 1, 1);
            }
        }
    }

    // ---- rowsum reduction ----
#pragma unroll
    for (int mt = 0; mt < 2; mt++)
#pragma unroll
        for (int e = 0; e < 2; e++) {
            rs[mt][e] += __shfl_xor_sync(0xffffffffu, rs[mt][e], 1);
            rs[mt][e] += __shfl_xor_sync(0xffffffffu, rs[mt][e], 2);
        }
    if ((lane & 3) == 0) {
#pragma unroll
        for (int mt = 0; mt < 2; mt++)
#pragma unroll
            for (int e = 0; e < 2; e++)
                sRS[wn * 128 + wm * 32 + mt * 16 + (lane >> 2) + 8 * e] = rs[mt][e];
    }
    __syncthreads();

    // ---- normalize + store ----
    const int b = bh >> 4, h = bh & 15;
#pragma unroll
    for (int mt = 0; mt < 2; mt++) {
#pragma unroll
        for (int half = 0; half < 2; half++) {
            const int row = wm * 32 + mt * 16 + (lane >> 2) + 8 * half;
            const float inv = 1.0f / (sRS[row] + sRS[128 + row]);
            const int n = n0 + row;
#pragma unroll
            for (int nt = 0; nt < 8; nt++) {
                const int col = wn * 64 + nt * 8 + (lane & 3) * 2;
                float* dstb = (col < 64) ? g_Or : g_Oi;
                const int d = col & 63;
                float2 v;
                v.x = accO[mt][nt][half * 2] * inv;
                v.y = accO[mt][nt][half * 2 + 1] * inv;
                *(float2*)(dstb + ((size_t)(b * SEQ + n)) * DIMV + h * DH + d) = v;
            }
        }
    }
}

// =================== launcher ===================
extern "C" void kernel_launch(void* const* d_in, const int* in_sizes, int n_in,
                              void* d_out, int out_size)
{
    const float* xr = (const float*)d_in[0];
    const float* xi = (const float*)d_in[1];
    const float* Wr = (const float*)d_in[2];
    const float* Wi = (const float*)d_in[3];
    const float* br = (const float*)d_in[4];
    const float* bi = (const float*)d_in[5];

    float* outR = (float*)d_out;
    float* outI = outR + (size_t)BATCH * SEQ * DIMV;

    cudaFuncSetAttribute(mma_gemm, cudaFuncAttributeMaxDynamicSharedMemorySize, SMEM_GEMM);
    cudaFuncSetAttribute(attn2_kernel, cudaFuncAttributeMaxDynamicSharedMemorySize, ATTN2_SMEM);

    conv_a_kernel<<<4096, 256>>>(xr, xi, 0);
    conv_w_kernel<<<4096, 256>>>(Wr, Wi);

    // fused QKV projection
    mma_gemm<<<dim3(3072 / BN, 8192 / BM), 256, SMEM_GEMM>>>(br, bi, nullptr, nullptr, 0);

    // pack attention operands
    conv_qk_kernel<<<4096, 256>>>();
    conv_v_kernel<<<4096, 256>>>();

    // tensor-core attention
    attn2_kernel<<<dim3(SEQ / 128, BH), 256, ATTN2_SMEM>>>();

    // output projection
    conv_a_kernel<<<4096, 256>>>(nullptr, nullptr, 1);
    mma_gemm<<<dim3(1024 / BN, 8192 / BM), 256, SMEM_GEMM>>>(br + 3 * DIMV, bi + 3 * DIMV,
                                                             outR, outI, 1);
}

// round 6
// speedup vs baseline: 6.3020x; 2.5228x over previous
#include <cuda_runtime.h>
#include <cuda_fp16.h>
#include <math.h>
#include <stdint.h>

#define DIMV   1024
#define HEADS  16
#define DH     64
#define BATCH  4
#define SEQ    1024
#define BH     (BATCH*HEADS)
#define K_EFF  2048
#define KBYTES (K_EFF*2)

// ---------------- device scratch ----------------
__device__ float g_Qr[BH*SEQ*DH];
__device__ float g_Qi[BH*SEQ*DH];
__device__ float g_Kr[BH*SEQ*DH];
__device__ float g_Ki[BH*SEQ*DH];
__device__ float g_Vr[BH*SEQ*DH];
__device__ float g_Vi[BH*SEQ*DH];
__device__ float g_Or[BATCH*SEQ*DIMV];
__device__ float g_Oi[BATCH*SEQ*DIMV];
__device__ __half g_Acat[(size_t)8192*K_EFF];        // [real rows 0..4095 | imag rows 4096..8191]
__device__ __half g_Wcat[(size_t)4096*K_EFF];        // 4 layers x 1024 rows: [Wr Wi]
__device__ __half g_Qpack[(size_t)BH*SEQ*128];       // [bh][n][qr|qi]
__device__ __half g_Kpack[(size_t)BH*2*SEQ*128];     // [bh][variant][n][..]: v0=[kr ki], v1=[-ki kr]
__device__ __half g_Vpack[(size_t)BH*16*128*64];     // [bh][ktile][d(128: vr|vi)][key(64)]

// ---------------- ptx helpers ----------------
__device__ __forceinline__ uint32_t smem_u32(const void* p) {
    uint32_t a;
    asm("{ .reg .u64 t; cvta.to.shared.u64 t, %1; cvt.u32.u64 %0, t; }" : "=r"(a) : "l"(p));
    return a;
}
__device__ __forceinline__ void cp16(uint32_t dst, const void* src) {
    asm volatile("cp.async.cg.shared.global [%0], [%1], 16;" :: "r"(dst), "l"(src) : "memory");
}
__device__ __forceinline__ void cp_commit() { asm volatile("cp.async.commit_group;" ::: "memory"); }
template<int N> __device__ __forceinline__ void cp_wait() {
    asm volatile("cp.async.wait_group %0;" :: "n"(N) : "memory");
}
__device__ __forceinline__ void ldsm4(uint32_t* r, uint32_t addr) {
    asm volatile("ldmatrix.sync.aligned.m8n8.x4.shared.b16 {%0,%1,%2,%3}, [%4];"
                 : "=r"(r[0]), "=r"(r[1]), "=r"(r[2]), "=r"(r[3]) : "r"(addr));
}
__device__ __forceinline__ void mma16816(float* c, const uint32_t* a, uint32_t b0, uint32_t b1) {
    asm volatile(
        "mma.sync.aligned.m16n8k16.row.col.f32.f16.f16.f32 "
        "{%0,%1,%2,%3}, {%4,%5,%6,%7}, {%8,%9}, {%0,%1,%2,%3};"
        : "+f"(c[0]), "+f"(c[1]), "+f"(c[2]), "+f"(c[3])
        : "r"(a[0]), "r"(a[1]), "r"(a[2]), "r"(a[3]), "r"(b0), "r"(b1));
}
__device__ __forceinline__ uint32_t sw128(uint32_t off) { return off ^ ((off >> 3) & 0x70); }

// ---------------- fp16 store helpers ----------------
__device__ __forceinline__ void st4h(__half* p, const float* v) {
    __half2 a = __floats2half2_rn(v[0], v[1]);
    __half2 b = __floats2half2_rn(v[2], v[3]);
    uint2 u;
    u.x = *(const uint32_t*)&a;
    u.y = *(const uint32_t*)&b;
    *(uint2*)p = u;
}
__device__ __forceinline__ void st4hn(__half* p, const float* v) {
    __half2 a = __floats2half2_rn(-v[0], -v[1]);
    __half2 b = __floats2half2_rn(-v[2], -v[3]);
    uint2 u;
    u.x = *(const uint32_t*)&a;
    u.y = *(const uint32_t*)&b;
    *(uint2*)p = u;
}

// ---------------- conversion: GEMM operands ----------------
// A real row m: [xr, -xi], imag row m: [xi, xr]
__global__ void conv_a_kernel(const float* __restrict__ ar_in,
                              const float* __restrict__ ai_in, int useO)
{
    const float* ar = useO ? g_Or : ar_in;
    const float* ai = useO ? g_Oi : ai_in;
    const int idx = blockIdx.x * 256 + threadIdx.x;
    const int row = idx >> 8;
    const int c = (idx & 255) << 2;
    const size_t src = (size_t)row * 1024 + c;
    const float4 vr = *(const float4*)(ar + src);
    const float4 vi = *(const float4*)(ai + src);
    const float fr[4] = {vr.x, vr.y, vr.z, vr.w};
    const float fi[4] = {vi.x, vi.y, vi.z, vi.w};
    __half* Re = g_Acat + (size_t)row * K_EFF + c;
    __half* Im = g_Acat + (size_t)(row + 4096) * K_EFF + c;
    st4h (Re + 0,    fr);
    st4hn(Re + 1024, fi);
    st4h (Im + 0,    fi);
    st4h (Im + 1024, fr);
}

// W row n: [Wr, Wi]
__global__ void conv_w_kernel(const float* __restrict__ Wr, const float* __restrict__ Wi)
{
    const int idx = blockIdx.x * 256 + threadIdx.x;
    const int row = idx >> 8;
    const int c = (idx & 255) << 2;
    const size_t src = (size_t)row * 1024 + c;
    const float4 vr = *(const float4*)(Wr + src);
    const float4 vi = *(const float4*)(Wi + src);
    const float fr[4] = {vr.x, vr.y, vr.z, vr.w};
    const float fi[4] = {vi.x, vi.y, vi.z, vi.w};
    __half* W = g_Wcat + (size_t)row * K_EFF + c;
    st4h(W + 0,    fr);
    st4h(W + 1024, fi);
}

// ---------------- conversion: attention packed operands ----------------
__global__ void conv_qk_kernel()
{
    const int r = blockIdx.x * 16 + (threadIdx.x >> 4);
    const int d0 = (threadIdx.x & 15) << 2;
    const int bh = r >> 10, n = r & 1023;
    const size_t src = ((size_t)bh * SEQ + n) * DH + d0;
    const float4 q_r = *(const float4*)(g_Qr + src);
    const float4 q_i = *(const float4*)(g_Qi + src);
    const float4 k_r = *(const float4*)(g_Kr + src);
    const float4 k_i = *(const float4*)(g_Ki + src);
    const float fqr[4] = {q_r.x, q_r.y, q_r.z, q_r.w};
    const float fqi[4] = {q_i.x, q_i.y, q_i.z, q_i.w};
    const float fkr[4] = {k_r.x, k_r.y, k_r.z, k_r.w};
    const float fki[4] = {k_i.x, k_i.y, k_i.z, k_i.w};
    __half* Qp = g_Qpack + ((size_t)bh * SEQ + n) * 128 + d0;
    st4h(Qp + 0,  fqr);
    st4h(Qp + 64, fqi);
    __half* K0 = g_Kpack + (((size_t)bh * 2 + 0) * SEQ + n) * 128 + d0;
    st4h(K0 + 0,  fkr);
    st4h(K0 + 64, fki);
    __half* K1 = g_Kpack + (((size_t)bh * 2 + 1) * SEQ + n) * 128 + d0;
    st4hn(K1 + 0,  fki);
    st4h (K1 + 64, fkr);
}

// Vpack[bh][kt][d][key]: d<64 -> Vr, d>=64 -> Vi
__global__ void conv_v_kernel()
{
    const int idx = blockIdx.x * 256 + threadIdx.x;
    const int bh = idx >> 14;
    const int local = idx & 16383;
    const int grp = local >> 6;          // key group of 4 (0..255)
    const int d = local & 63;
    const int key0 = grp * 4;
    const int kt = key0 >> 6, jloc = key0 & 63;
    float fvr[4], fvi[4];
#pragma unroll
    for (int k = 0; k < 4; k++) {
        const size_t src = ((size_t)bh * SEQ + key0 + k) * DH + d;
        fvr[k] = g_Vr[src];
        fvi[k] = g_Vi[src];
    }
    __half* base = g_Vpack + (((size_t)bh * 16 + kt) * 128) * 64;
    st4h(base + d * 64 + jloc, fvr);
    st4h(base + (64 + d) * 64 + jloc, fvi);
}

// ---------------- mma.sync projection GEMM ----------------
#define BM 128
#define BN 128
#define BK 64
#define NITER (K_EFF/BK)     // 32
#define A_ST  16384
#define ST_SZ 32768
#define SMEM_GEMM (3*ST_SZ)

__device__ __forceinline__ void load_stage(uint32_t sbase, int s, int kt, int tid,
                                           const __half* Ab, const __half* Bb)
{
    const char* aSrc = (const char*)Ab + (size_t)kt * (BK * 2);
    const char* bSrc = (const char*)Bb + (size_t)kt * (BK * 2);
    const uint32_t aDst = sbase + s * ST_SZ;
    const uint32_t bDst = aDst + A_ST;
#pragma unroll
    for (int i = 0; i < 4; i++) {
        const int q = tid + i * 256;
        const int row = q >> 3, cc = q & 7;
        const uint32_t sw = sw128(row * 128 + cc * 16);
        cp16(aDst + sw, aSrc + (size_t)row * KBYTES + cc * 16);
        cp16(bDst + sw, bSrc + (size_t)row * KBYTES + cc * 16);
    }
}

__device__ __forceinline__ void epi_store(int mode, int gm, int gc,
                                          float v0, float v1,
                                          const float* biasR, const float* biasI,
                                          float* outR, float* outI)
{
    const int plane = gm >> 12;
    const int m = gm & 4095;
    const int b = m >> 10, n = m & 1023;
    const float* bias = plane ? biasI : biasR;
    float2 v;
    v.x = v0 + bias[gc];
    v.y = v1 + bias[gc + 1];
    float* base;
    size_t dst;
    if (mode == 0) {
        const int layer = gc >> 10;
        const int cw = gc & 1023;
        const int h = cw >> 6, d = cw & 63;
        if (layer == 0)      base = plane ? g_Qi : g_Qr;
        else if (layer == 1) base = plane ? g_Ki : g_Kr;
        else                 base = plane ? g_Vi : g_Vr;
        dst = ((size_t)(b * HEADS + h) * SEQ + n) * DH + d;
    } else {
        base = plane ? outI : outR;
        dst = (size_t)m * 1024 + gc;
    }
    *(float2*)(base + dst) = v;
}

__global__ void __launch_bounds__(256, 2) mma_gemm(
    const float* __restrict__ biasR, const float* __restrict__ biasI,
    float* __restrict__ outR, float* __restrict__ outI, int mode)
{
    extern __shared__ char smem[];
    const uint32_t sbase = smem_u32(smem);
    const int tid = threadIdx.x;
    const int lane = tid & 31;
    const int wid = tid >> 5;
    const int wm = wid & 3;
    const int wn = wid >> 2;

    const __half* Ab = g_Acat + (size_t)blockIdx.y * BM * K_EFF;
    const __half* Bb = g_Wcat + (mode ? (size_t)3072 * K_EFF : 0)
                              + (size_t)blockIdx.x * BN * K_EFF;

    float acc[2][8][4];
#pragma unroll
    for (int mt = 0; mt < 2; mt++)
#pragma unroll
        for (int nt = 0; nt < 8; nt++)
#pragma unroll
            for (int r = 0; r < 4; r++) acc[mt][nt][r] = 0.f;

    load_stage(sbase, 0, 0, tid, Ab, Bb); cp_commit();
    load_stage(sbase, 1, 1, tid, Ab, Bb); cp_commit();

    const int lr_ = lane & 15;
    const int lc16 = (lane >> 4) * 16;

    for (int kt = 0; kt < NITER; kt++) {
        cp_wait<1>();
        __syncthreads();
        const int slot = kt % 3;
        const uint32_t aB = sbase + slot * ST_SZ;
        const uint32_t bB = aB + A_ST;
#pragma unroll
        for (int ks = 0; ks < 4; ks++) {
            const uint32_t cb = ks * 32 + lc16;
            uint32_t af[2][4], bf[4][4];
#pragma unroll
            for (int mt = 0; mt < 2; mt++) {
                const uint32_t off = (uint32_t)(wm * 32 + mt * 16 + lr_) * 128 + cb;
                ldsm4(af[mt], aB + sw128(off));
            }
#pragma unroll
            for (int pr = 0; pr < 4; pr++) {
                const uint32_t off = (uint32_t)(wn * 64 + pr * 16 + lr_) * 128 + cb;
                ldsm4(bf[pr], bB + sw128(off));
            }
#pragma unroll
            for (int mt = 0; mt < 2; mt++)
#pragma unroll
                for (int nt = 0; nt < 8; nt++)
                    mma16816(acc[mt][nt], af[mt],
                             bf[nt >> 1][nt & 1], bf[nt >> 1][(nt & 1) + 2]);
        }
        const int pk = kt + 2;
        if (pk < NITER) load_stage(sbase, pk % 3, pk, tid, Ab, Bb);
        cp_commit();
    }

    const int blockRow = blockIdx.y * BM;
    const int blockCol = blockIdx.x * BN;
#pragma unroll
    for (int mt = 0; mt < 2; mt++) {
        const int gr0 = blockRow + wm * 32 + mt * 16 + (lane >> 2);
#pragma unroll
        for (int nt = 0; nt < 8; nt++) {
            const int gc = blockCol + wn * 64 + nt * 8 + (lane & 3) * 2;
            epi_store(mode, gr0,     gc, acc[mt][nt][0], acc[mt][nt][1], biasR, biasI, outR, outI);
            epi_store(mode, gr0 + 8, gc, acc[mt][nt][2], acc[mt][nt][3], biasR, biasI, outR, outI);
        }
    }
}

// =================== tensor-core attention (fp16 single) ===================
// smem: Q 32KB | K 2x32KB | V 2x16KB | P 16KB | rowsum 1KB
#define SQ_OFF 0
#define SK_OFF 32768
#define SV_OFF (SK_OFF + 2*32768)
#define SP_OFF (SV_OFF + 2*16384)
#define SRS_OFF (SP_OFF + 16384)
#define ATTN2_SMEM (SRS_OFF + 1024)

__global__ void __launch_bounds__(256, 1) attn2_kernel()
{
    extern __shared__ char sm[];
    const uint32_t sb = smem_u32(sm);
    const uint32_t sQ = sb + SQ_OFF;
    const uint32_t sK = sb + SK_OFF;
    const uint32_t sV = sb + SV_OFF;
    const uint32_t sP = sb + SP_OFF;
    float* sRS = (float*)(sm + SRS_OFF);

    const int tid = threadIdx.x;
    const int lane = tid & 31;
    const int wid = tid >> 5;
    const int wm = wid & 3;
    const int wn = wid >> 2;
    const int bh = blockIdx.y;
    const int n0 = blockIdx.x * 128;

    const char* Qg  = (const char*)(g_Qpack + ((size_t)bh * SEQ + n0) * 128);
    const char* Kg0 = (const char*)(g_Kpack + ((size_t)bh * 2 + 0) * SEQ * 128);
    const char* Kg1 = (const char*)(g_Kpack + ((size_t)bh * 2 + 1) * SEQ * 128);
    const char* Vg  = (const char*)(g_Vpack + (size_t)bh * 16 * 128 * 64);

    // Q: 128 rows x 256B (two 16KB chunks)
#pragma unroll
    for (int i = 0; i < 8; i++) {
        const int q = tid + i * 256;
        const int row = q >> 4, cc = q & 15;
        const int ch = cc >> 3, w = cc & 7;
        cp16(sQ + ch * 16384 + sw128(row * 128 + w * 16),
             Qg + (size_t)row * 256 + cc * 16);
    }
    cp_commit();

#define LOAD_K(ktile, buf) do { \
    _Pragma("unroll") \
    for (int i = 0; i < 8; i++) { \
        const int q = tid + i * 256; \
        const int row = q >> 4, cc = q & 15; \
        const int ch = cc >> 3, w = cc & 7; \
        const char* src = (row < 64) \
            ? Kg0 + (size_t)((ktile) * 64 + row) * 256 + cc * 16 \
            : Kg1 + (size_t)((ktile) * 64 + row - 64) * 256 + cc * 16; \
        cp16(sK + (buf) * 32768 + ch * 16384 + sw128(row * 128 + w * 16), src); \
    } \
    cp_commit(); } while (0)

#define LOAD_V(ktile, buf) do { \
    _Pragma("unroll") \
    for (int i = 0; i < 4; i++) { \
        const int q = tid + i * 256; \
        const int row = q >> 3, cc = q & 7; \
        cp16(sV + (buf) * 16384 + sw128(row * 128 + cc * 16), \
             Vg + (size_t)(ktile) * 16384 + (size_t)row * 128 + cc * 16); \
    } \
    cp_commit(); } while (0)

    LOAD_K(0, 0);
    LOAD_V(0, 0);
    LOAD_K(1, 1);
    LOAD_V(1, 1);

    float accO[2][8][4];
#pragma unroll
    for (int mt = 0; mt < 2; mt++)
#pragma unroll
        for (int nt = 0; nt < 8; nt++)
#pragma unroll
            for (int e = 0; e < 4; e++) accO[mt][nt][e] = 0.f;
    float rs[2][2] = {{0.f, 0.f}, {0.f, 0.f}};

    const int lr_ = lane & 15;
    const int lc16 = (lane >> 4) * 16;

    for (int kt = 0; kt < 16; kt++) {
        const int buf = kt & 1;
        // ---- wait K_kt (Q implied by in-order drain on kt=0) ----
        if (kt <= 14) cp_wait<3>(); else cp_wait<1>();
        __syncthreads();

        // ---- S GEMM: acc 128x128 over K_eff=128 (8 ks steps across 2 chunks) ----
        float accS[2][8][4];
#pragma unroll
        for (int mt = 0; mt < 2; mt++)
#pragma unroll
            for (int nt = 0; nt < 8; nt++)
#pragma unroll
                for (int e = 0; e < 4; e++) accS[mt][nt][e] = 0.f;

        const uint32_t kBase = sK + buf * 32768;
#pragma unroll
        for (int ks = 0; ks < 8; ks++) {
            const uint32_t cbf = ks * 32 + lc16;       // 0..240+16
            const uint32_t ch = cbf >> 7;
            const uint32_t w = cbf & 127;
            uint32_t af[2][4], bf[4][4];
#pragma unroll
            for (int mt = 0; mt < 2; mt++) {
                const uint32_t off = (uint32_t)(wm * 32 + mt * 16 + lr_) * 128 + w;
                ldsm4(af[mt], sQ + ch * 16384 + sw128(off));
            }
#pragma unroll
            for (int pr = 0; pr < 4; pr++) {
                const int rbase = (pr < 2) ? (wn * 32 + pr * 16)
                                           : (64 + wn * 32 + (pr - 2) * 16);
                const uint32_t off = (uint32_t)(rbase + lr_) * 128 + w;
                ldsm4(bf[pr], kBase + ch * 16384 + sw128(off));
            }
#pragma unroll
            for (int mt = 0; mt < 2; mt++)
#pragma unroll
                for (int nt = 0; nt < 8; nt++)
                    mma16816(accS[mt][nt], af[mt],
                             bf[nt >> 1][nt & 1], bf[nt >> 1][(nt & 1) + 2]);
        }
        __syncthreads();           // all warps done with K slot
        if (kt + 2 <= 15) LOAD_K(kt + 2, buf);

        // ---- softmax -> P (fp16, 128q x 64keys) ----
#pragma unroll
        for (int mt = 0; mt < 2; mt++) {
#pragma unroll
            for (int nt = 0; nt < 4; nt++) {
                float p[4];
#pragma unroll
                for (int e = 0; e < 4; e++) {
                    const float srv = accS[mt][nt][e];
                    const float siv = accS[mt][nt + 4][e];
                    p[e] = __expf(sqrtf(srv * srv + siv * siv) * 0.125f);
                }
                rs[mt][0] += p[0] + p[1];
                rs[mt][1] += p[2] + p[3];
                const int keyb = (wn * 32 + nt * 8 + (lane & 3) * 2) * 2;
                const int row0 = wm * 32 + mt * 16 + (lane >> 2);
#pragma unroll
                for (int half = 0; half < 2; half++) {
                    const __half2 hp = __floats2half2_rn(p[half * 2], p[half * 2 + 1]);
                    const uint32_t off = (uint32_t)(row0 + half * 8) * 128 + keyb;
                    *(uint32_t*)(sm + SP_OFF + sw128(off)) = *(const uint32_t*)&hp;
                }
            }
        }
        __syncthreads();           // P visible

        // ---- wait V_kt ----
        if (kt <= 13) cp_wait<3>();
        else if (kt == 14) cp_wait<2>();
        else cp_wait<0>();
        __syncthreads();

        // ---- PV: accO += P[128x64] @ V[64 -> 128 cols] ----
        const uint32_t vBase = sV + buf * 16384;
#pragma unroll
        for (int ks = 0; ks < 4; ks++) {
            const uint32_t cb = ks * 32 + lc16;
            uint32_t af[2][4], bf[4][4];
#pragma unroll
            for (int mt = 0; mt < 2; mt++) {
                const uint32_t off = (uint32_t)(wm * 32 + mt * 16 + lr_) * 128 + cb;
                ldsm4(af[mt], sP + sw128(off));
            }
#pragma unroll
            for (int pr = 0; pr < 4; pr++) {
                const uint32_t off = (uint32_t)(wn * 64 + pr * 16 + lr_) * 128 + cb;
                ldsm4(bf[pr], vBase + sw128(off));
            }
#pragma unroll
            for (int mt = 0; mt < 2; mt++)
#pragma unroll
                for (int nt = 0; nt < 8; nt++)
                    mma16816(accO[mt][nt], af[mt],
                             bf[nt >> 1][nt & 1], bf[nt >> 1][(nt & 1) + 2]);
        }
        __syncthreads();           // done with V slot + P
        if (kt + 2 <= 15) LOAD_V(kt + 2, buf);
    }

    // ---- rowsum reduction ----
#pragma unroll
    for (int mt = 0; mt < 2; mt++)
#pragma unroll
        for (int e = 0; e < 2; e++) {
            rs[mt][e] += __shfl_xor_sync(0xffffffffu, rs[mt][e], 1);
            rs[mt][e] += __shfl_xor_sync(0xffffffffu, rs[mt][e], 2);
        }
    if ((lane & 3) == 0) {
#pragma unroll
        for (int mt = 0; mt < 2; mt++)
#pragma unroll
            for (int e = 0; e < 2; e++)
                sRS[wn * 128 + wm * 32 + mt * 16 + (lane >> 2) + 8 * e] = rs[mt][e];
    }
    __syncthreads();

    // ---- normalize + store ----
    const int b = bh >> 4, h = bh & 15;
#pragma unroll
    for (int mt = 0; mt < 2; mt++) {
#pragma unroll
        for (int half = 0; half < 2; half++) {
            const int row = wm * 32 + mt * 16 + (lane >> 2) + 8 * half;
            const float inv = 1.0f / (sRS[row] + sRS[128 + row]);
            const int n = n0 + row;
#pragma unroll
            for (int nt = 0; nt < 8; nt++) {
                const int col = wn * 64 + nt * 8 + (lane & 3) * 2;
                float* dstb = (col < 64) ? g_Or : g_Oi;
                const int d = col & 63;
                float2 v;
                v.x = accO[mt][nt][half * 2] * inv;
                v.y = accO[mt][nt][half * 2 + 1] * inv;
                *(float2*)(dstb + ((size_t)(b * SEQ + n)) * DIMV + h * DH + d) = v;
            }
        }
    }
}

// =================== launcher ===================
extern "C" void kernel_launch(void* const* d_in, const int* in_sizes, int n_in,
                              void* d_out, int out_size)
{
    const float* xr = (const float*)d_in[0];
    const float* xi = (const float*)d_in[1];
    const float* Wr = (const float*)d_in[2];
    const float* Wi = (const float*)d_in[3];
    const float* br = (const float*)d_in[4];
    const float* bi = (const float*)d_in[5];

    float* outR = (float*)d_out;
    float* outI = outR + (size_t)BATCH * SEQ * DIMV;

    cudaFuncSetAttribute(mma_gemm, cudaFuncAttributeMaxDynamicSharedMemorySize, SMEM_GEMM);
    cudaFuncSetAttribute(attn2_kernel, cudaFuncAttributeMaxDynamicSharedMemorySize, ATTN2_SMEM);

    conv_a_kernel<<<4096, 256>>>(xr, xi, 0);
    conv_w_kernel<<<4096, 256>>>(Wr, Wi);

    // fused QKV projection: C[8192 x 3072]
    mma_gemm<<<dim3(3072 / BN, 8192 / BM), 256, SMEM_GEMM>>>(br, bi, nullptr, nullptr, 0);

    // pack attention operands
    conv_qk_kernel<<<4096, 256>>>();
    conv_v_kernel<<<4096, 256>>>();

    // tensor-core attention
    attn2_kernel<<<dim3(SEQ / 128, BH), 256, ATTN2_SMEM>>>();

    // output projection
    conv_a_kernel<<<4096, 256>>>(nullptr, nullptr, 1);
    mma_gemm<<<dim3(1024 / BN, 8192 / BM), 256, SMEM_GEMM>>>(br + 3 * DIMV, bi + 3 * DIMV,
                                                             outR, outI, 1);
}

// round 7
// speedup vs baseline: 6.4394x; 1.0218x over previous
#include <cuda_runtime.h>
#include <cuda_fp16.h>
#include <math.h>
#include <stdint.h>

#define DIMV   1024
#define HEADS  16
#define DH     64
#define BATCH  4
#define SEQ    1024
#define BH     (BATCH*HEADS)
#define K_EFF  2048
#define KBYTES (K_EFF*2)

// ---------------- device scratch ----------------
__device__ float g_Vr[BH*SEQ*DH];
__device__ float g_Vi[BH*SEQ*DH];
__device__ __half g_Acat[(size_t)8192*K_EFF];        // [real rows 0..4095 | imag rows 4096..8191]
__device__ __half g_Wcat[(size_t)4096*K_EFF];        // 4 layers x 1024 rows: [Wr Wi]
__device__ __half g_Qpack[(size_t)BH*SEQ*128];       // [bh][n][qr|qi]
__device__ __half g_Kpack[(size_t)BH*2*SEQ*128];     // [bh][variant][n]: v0=[kr ki], v1=[-ki kr]
__device__ __half g_Vpack[(size_t)BH*16*128*64];     // [bh][ktile][d(128: vr|vi)][key(64)]

// ---------------- ptx helpers ----------------
__device__ __forceinline__ uint32_t smem_u32(const void* p) {
    uint32_t a;
    asm("{ .reg .u64 t; cvta.to.shared.u64 t, %1; cvt.u32.u64 %0, t; }" : "=r"(a) : "l"(p));
    return a;
}
__device__ __forceinline__ void cp16(uint32_t dst, const void* src) {
    asm volatile("cp.async.cg.shared.global [%0], [%1], 16;" :: "r"(dst), "l"(src) : "memory");
}
__device__ __forceinline__ void cp_commit() { asm volatile("cp.async.commit_group;" ::: "memory"); }
template<int N> __device__ __forceinline__ void cp_wait() {
    asm volatile("cp.async.wait_group %0;" :: "n"(N) : "memory");
}
__device__ __forceinline__ void ldsm4(uint32_t* r, uint32_t addr) {
    asm volatile("ldmatrix.sync.aligned.m8n8.x4.shared.b16 {%0,%1,%2,%3}, [%4];"
                 : "=r"(r[0]), "=r"(r[1]), "=r"(r[2]), "=r"(r[3]) : "r"(addr));
}
__device__ __forceinline__ void mma16816(float* c, const uint32_t* a, uint32_t b0, uint32_t b1) {
    asm volatile(
        "mma.sync.aligned.m16n8k16.row.col.f32.f16.f16.f32 "
        "{%0,%1,%2,%3}, {%4,%5,%6,%7}, {%8,%9}, {%0,%1,%2,%3};"
        : "+f"(c[0]), "+f"(c[1]), "+f"(c[2]), "+f"(c[3])
        : "r"(a[0]), "r"(a[1]), "r"(a[2]), "r"(a[3]), "r"(b0), "r"(b1));
}
__device__ __forceinline__ uint32_t sw128(uint32_t off) { return off ^ ((off >> 3) & 0x70); }

// ---------------- fp16 store helpers ----------------
__device__ __forceinline__ void st4h(__half* p, const float* v) {
    __half2 a = __floats2half2_rn(v[0], v[1]);
    __half2 b = __floats2half2_rn(v[2], v[3]);
    uint2 u;
    u.x = *(const uint32_t*)&a;
    u.y = *(const uint32_t*)&b;
    *(uint2*)p = u;
}
__device__ __forceinline__ void st4hn(__half* p, const float* v) {
    __half2 a = __floats2half2_rn(-v[0], -v[1]);
    __half2 b = __floats2half2_rn(-v[2], -v[3]);
    uint2 u;
    u.x = *(const uint32_t*)&a;
    u.y = *(const uint32_t*)&b;
    *(uint2*)p = u;
}

// ---------------- conversion: GEMM operands (from inputs only) ----------------
// A real row m: [xr, -xi], imag row m: [xi, xr]
__global__ void conv_a_kernel(const float* __restrict__ ar, const float* __restrict__ ai)
{
    const int idx = blockIdx.x * 256 + threadIdx.x;
    const int row = idx >> 8;
    const int c = (idx & 255) << 2;
    const size_t src = (size_t)row * 1024 + c;
    const float4 vr = *(const float4*)(ar + src);
    const float4 vi = *(const float4*)(ai + src);
    const float fr[4] = {vr.x, vr.y, vr.z, vr.w};
    const float fi[4] = {vi.x, vi.y, vi.z, vi.w};
    __half* Re = g_Acat + (size_t)row * K_EFF + c;
    __half* Im = g_Acat + (size_t)(row + 4096) * K_EFF + c;
    st4h (Re + 0,    fr);
    st4hn(Re + 1024, fi);
    st4h (Im + 0,    fi);
    st4h (Im + 1024, fr);
}

// W row n: [Wr, Wi]
__global__ void conv_w_kernel(const float* __restrict__ Wr, const float* __restrict__ Wi)
{
    const int idx = blockIdx.x * 256 + threadIdx.x;
    const int row = idx >> 8;
    const int c = (idx & 255) << 2;
    const size_t src = (size_t)row * 1024 + c;
    const float4 vr = *(const float4*)(Wr + src);
    const float4 vi = *(const float4*)(Wi + src);
    const float fr[4] = {vr.x, vr.y, vr.z, vr.w};
    const float fi[4] = {vi.x, vi.y, vi.z, vi.w};
    __half* W = g_Wcat + (size_t)row * K_EFF + c;
    st4h(W + 0,    fr);
    st4h(W + 1024, fi);
}

// Vpack[bh][kt][d][key]: d<64 -> Vr, d>=64 -> Vi
__global__ void conv_v_kernel()
{
    const int idx = blockIdx.x * 256 + threadIdx.x;
    const int bh = idx >> 14;
    const int local = idx & 16383;
    const int grp = local >> 6;          // key group of 4 (0..255)
    const int d = local & 63;
    const int key0 = grp * 4;
    const int kt = key0 >> 6, jloc = key0 & 63;
    float fvr[4], fvi[4];
#pragma unroll
    for (int k = 0; k < 4; k++) {
        const size_t src = ((size_t)bh * SEQ + key0 + k) * DH + d;
        fvr[k] = g_Vr[src];
        fvi[k] = g_Vi[src];
    }
    __half* base = g_Vpack + (((size_t)bh * 16 + kt) * 128) * 64;
    st4h(base + d * 64 + jloc, fvr);
    st4h(base + (64 + d) * 64 + jloc, fvi);
}

// ---------------- mma.sync projection GEMM ----------------
#define BM 128
#define BN 128
#define BK 64
#define NITER (K_EFF/BK)     // 32
#define A_ST  16384
#define ST_SZ 32768
#define SMEM_GEMM (3*ST_SZ)

__device__ __forceinline__ void load_stage(uint32_t sbase, int s, int kt, int tid,
                                           const __half* Ab, const __half* Bb)
{
    const char* aSrc = (const char*)Ab + (size_t)kt * (BK * 2);
    const char* bSrc = (const char*)Bb + (size_t)kt * (BK * 2);
    const uint32_t aDst = sbase + s * ST_SZ;
    const uint32_t bDst = aDst + A_ST;
#pragma unroll
    for (int i = 0; i < 4; i++) {
        const int q = tid + i * 256;
        const int row = q >> 3, cc = q & 7;
        const uint32_t sw = sw128(row * 128 + cc * 16);
        cp16(aDst + sw, aSrc + (size_t)row * KBYTES + cc * 16);
        cp16(bDst + sw, bSrc + (size_t)row * KBYTES + cc * 16);
    }
}

// epilogue: mode 0 writes Qpack/Kpack fp16 + V fp32; mode 1 writes final planes
__device__ __forceinline__ void epi_store(int mode, int gm, int gc,
                                          float v0, float v1,
                                          const float* biasR, const float* biasI,
                                          float* outR, float* outI)
{
    const int plane = gm >> 12;
    const int m = gm & 4095;
    const int b = m >> 10, n = m & 1023;
    const float* bias = plane ? biasI : biasR;
    const float f0 = v0 + bias[gc];
    const float f1 = v1 + bias[gc + 1];
    if (mode == 0) {
        const int layer = gc >> 10;
        const int cw = gc & 1023;
        const int h = cw >> 6, d = cw & 63;
        const int bh = b * HEADS + h;
        if (layer == 2) {
            float* base = plane ? g_Vi : g_Vr;
            float2 v; v.x = f0; v.y = f1;
            *(float2*)(base + ((size_t)bh * SEQ + n) * DH + d) = v;
        } else {
            const __half2 hp = __floats2half2_rn(f0, f1);
            if (layer == 0) {
                __half* dst = g_Qpack + ((size_t)bh * SEQ + n) * 128 + plane * 64 + d;
                *(uint32_t*)dst = *(const uint32_t*)&hp;
            } else {
                // v0 = [kr ki] : col plane*64+d
                __half* d0 = g_Kpack + (((size_t)bh * 2 + 0) * SEQ + n) * 128 + plane * 64 + d;
                *(uint32_t*)d0 = *(const uint32_t*)&hp;
                // v1 = [-ki kr] : kr (plane0) -> col 64+d ; ki (plane1) -> col d negated
                const __half2 hv = plane ? __hneg2(hp) : hp;
                __half* d1 = g_Kpack + (((size_t)bh * 2 + 1) * SEQ + n) * 128
                           + (plane ? 0 : 64) + d;
                *(uint32_t*)d1 = *(const uint32_t*)&hv;
            }
        }
    } else {
        float* base = plane ? outI : outR;
        float2 v; v.x = f0; v.y = f1;
        *(float2*)(base + (size_t)m * 1024 + gc) = v;
    }
}

__global__ void __launch_bounds__(256, 2) mma_gemm(
    const float* __restrict__ biasR, const float* __restrict__ biasI,
    float* __restrict__ outR, float* __restrict__ outI, int mode)
{
    extern __shared__ char smem[];
    const uint32_t sbase = smem_u32(smem);
    const int tid = threadIdx.x;
    const int lane = tid & 31;
    const int wid = tid >> 5;
    const int wm = wid & 3;
    const int wn = wid >> 2;

    const __half* Ab = g_Acat + (size_t)blockIdx.y * BM * K_EFF;
    const __half* Bb = g_Wcat + (mode ? (size_t)3072 * K_EFF : 0)
                              + (size_t)blockIdx.x * BN * K_EFF;

    float acc[2][8][4];
#pragma unroll
    for (int mt = 0; mt < 2; mt++)
#pragma unroll
        for (int nt = 0; nt < 8; nt++)
#pragma unroll
            for (int r = 0; r < 4; r++) acc[mt][nt][r] = 0.f;

    load_stage(sbase, 0, 0, tid, Ab, Bb); cp_commit();
    load_stage(sbase, 1, 1, tid, Ab, Bb); cp_commit();

    const int lr_ = lane & 15;
    const int lc16 = (lane >> 4) * 16;

    for (int kt = 0; kt < NITER; kt++) {
        cp_wait<1>();
        __syncthreads();
        const int slot = kt % 3;
        const uint32_t aB = sbase + slot * ST_SZ;
        const uint32_t bB = aB + A_ST;
#pragma unroll
        for (int ks = 0; ks < 4; ks++) {
            const uint32_t cb = ks * 32 + lc16;
            uint32_t af[2][4], bf[4][4];
#pragma unroll
            for (int mt = 0; mt < 2; mt++) {
                const uint32_t off = (uint32_t)(wm * 32 + mt * 16 + lr_) * 128 + cb;
                ldsm4(af[mt], aB + sw128(off));
            }
#pragma unroll
            for (int pr = 0; pr < 4; pr++) {
                const uint32_t off = (uint32_t)(wn * 64 + pr * 16 + lr_) * 128 + cb;
                ldsm4(bf[pr], bB + sw128(off));
            }
#pragma unroll
            for (int mt = 0; mt < 2; mt++)
#pragma unroll
                for (int nt = 0; nt < 8; nt++)
                    mma16816(acc[mt][nt], af[mt],
                             bf[nt >> 1][nt & 1], bf[nt >> 1][(nt & 1) + 2]);
        }
        const int pk = kt + 2;
        if (pk < NITER) load_stage(sbase, pk % 3, pk, tid, Ab, Bb);
        cp_commit();
    }

    const int blockRow = blockIdx.y * BM;
    const int blockCol = blockIdx.x * BN;
#pragma unroll
    for (int mt = 0; mt < 2; mt++) {
        const int gr0 = blockRow + wm * 32 + mt * 16 + (lane >> 2);
#pragma unroll
        for (int nt = 0; nt < 8; nt++) {
            const int gc = blockCol + wn * 64 + nt * 8 + (lane & 3) * 2;
            epi_store(mode, gr0,     gc, acc[mt][nt][0], acc[mt][nt][1], biasR, biasI, outR, outI);
            epi_store(mode, gr0 + 8, gc, acc[mt][nt][2], acc[mt][nt][3], biasR, biasI, outR, outI);
        }
    }
}

// =================== tensor-core attention (fp16 single) ===================
// smem: Q 32KB | K 2x32KB | V 2x16KB | P 16KB | rowsum 1KB
#define SQ_OFF 0
#define SK_OFF 32768
#define SV_OFF (SK_OFF + 2*32768)
#define SP_OFF (SV_OFF + 2*16384)
#define SRS_OFF (SP_OFF + 16384)
#define ATTN2_SMEM (SRS_OFF + 1024)

__global__ void __launch_bounds__(256, 1) attn2_kernel()
{
    extern __shared__ char sm[];
    const uint32_t sb = smem_u32(sm);
    const uint32_t sQ = sb + SQ_OFF;
    const uint32_t sK = sb + SK_OFF;
    const uint32_t sV = sb + SV_OFF;
    const uint32_t sP = sb + SP_OFF;
    float* sRS = (float*)(sm + SRS_OFF);

    const int tid = threadIdx.x;
    const int lane = tid & 31;
    const int wid = tid >> 5;
    const int wm = wid & 3;
    const int wn = wid >> 2;
    const int bh = blockIdx.y;
    const int n0 = blockIdx.x * 128;

    const char* Qg  = (const char*)(g_Qpack + ((size_t)bh * SEQ + n0) * 128);
    const char* Kg0 = (const char*)(g_Kpack + ((size_t)bh * 2 + 0) * SEQ * 128);
    const char* Kg1 = (const char*)(g_Kpack + ((size_t)bh * 2 + 1) * SEQ * 128);
    const char* Vg  = (const char*)(g_Vpack + (size_t)bh * 16 * 128 * 64);

    // Q: 128 rows x 256B (two 16KB chunks)
#pragma unroll
    for (int i = 0; i < 8; i++) {
        const int q = tid + i * 256;
        const int row = q >> 4, cc = q & 15;
        const int ch = cc >> 3, w = cc & 7;
        cp16(sQ + ch * 16384 + sw128(row * 128 + w * 16),
             Qg + (size_t)row * 256 + cc * 16);
    }
    cp_commit();

#define LOAD_K(ktile, buf) do { \
    _Pragma("unroll") \
    for (int i = 0; i < 8; i++) { \
        const int q = tid + i * 256; \
        const int row = q >> 4, cc = q & 15; \
        const int ch = cc >> 3, w = cc & 7; \
        const char* src = (row < 64) \
            ? Kg0 + (size_t)((ktile) * 64 + row) * 256 + cc * 16 \
            : Kg1 + (size_t)((ktile) * 64 + row - 64) * 256 + cc * 16; \
        cp16(sK + (buf) * 32768 + ch * 16384 + sw128(row * 128 + w * 16), src); \
    } \
    cp_commit(); } while (0)

#define LOAD_V(ktile, buf) do { \
    _Pragma("unroll") \
    for (int i = 0; i < 4; i++) { \
        const int q = tid + i * 256; \
        const int row = q >> 3, cc = q & 7; \
        cp16(sV + (buf) * 16384 + sw128(row * 128 + cc * 16), \
             Vg + (size_t)(ktile) * 16384 + (size_t)row * 128 + cc * 16); \
    } \
    cp_commit(); } while (0)

    LOAD_K(0, 0);
    LOAD_V(0, 0);
    LOAD_K(1, 1);
    LOAD_V(1, 1);

    float accO[2][8][4];
#pragma unroll
    for (int mt = 0; mt < 2; mt++)
#pragma unroll
        for (int nt = 0; nt < 8; nt++)
#pragma unroll
            for (int e = 0; e < 4; e++) accO[mt][nt][e] = 0.f;
    float rs[2][2] = {{0.f, 0.f}, {0.f, 0.f}};

    const int lr_ = lane & 15;
    const int lc16 = (lane >> 4) * 16;

    for (int kt = 0; kt < 16; kt++) {
        const int buf = kt & 1;
        if (kt <= 14) cp_wait<3>(); else cp_wait<1>();
        __syncthreads();

        float accS[2][8][4];
#pragma unroll
        for (int mt = 0; mt < 2; mt++)
#pragma unroll
            for (int nt = 0; nt < 8; nt++)
#pragma unroll
                for (int e = 0; e < 4; e++) accS[mt][nt][e] = 0.f;

        const uint32_t kBase = sK + buf * 32768;
#pragma unroll
        for (int ks = 0; ks < 8; ks++) {
            const uint32_t cbf = ks * 32 + lc16;
            const uint32_t ch = cbf >> 7;
            const uint32_t w = cbf & 127;
            uint32_t af[2][4], bf[4][4];
#pragma unroll
            for (int mt = 0; mt < 2; mt++) {
                const uint32_t off = (uint32_t)(wm * 32 + mt * 16 + lr_) * 128 + w;
                ldsm4(af[mt], sQ + ch * 16384 + sw128(off));
            }
#pragma unroll
            for (int pr = 0; pr < 4; pr++) {
                const int rbase = (pr < 2) ? (wn * 32 + pr * 16)
                                           : (64 + wn * 32 + (pr - 2) * 16);
                const uint32_t off = (uint32_t)(rbase + lr_) * 128 + w;
                ldsm4(bf[pr], kBase + ch * 16384 + sw128(off));
            }
#pragma unroll
            for (int mt = 0; mt < 2; mt++)
#pragma unroll
                for (int nt = 0; nt < 8; nt++)
                    mma16816(accS[mt][nt], af[mt],
                             bf[nt >> 1][nt & 1], bf[nt >> 1][(nt & 1) + 2]);
        }
        __syncthreads();
        if (kt + 2 <= 15) LOAD_K(kt + 2, buf);

        // ---- softmax -> P (fp16) ----
#pragma unroll
        for (int mt = 0; mt < 2; mt++) {
#pragma unroll
            for (int nt = 0; nt < 4; nt++) {
                float p[4];
#pragma unroll
                for (int e = 0; e < 4; e++) {
                    const float srv = accS[mt][nt][e];
                    const float siv = accS[mt][nt + 4][e];
                    p[e] = __expf(sqrtf(srv * srv + siv * siv) * 0.125f);
                }
                rs[mt][0] += p[0] + p[1];
                rs[mt][1] += p[2] + p[3];
                const int keyb = (wn * 32 + nt * 8 + (lane & 3) * 2) * 2;
                const int row0 = wm * 32 + mt * 16 + (lane >> 2);
#pragma unroll
                for (int half = 0; half < 2; half++) {
                    const __half2 hp = __floats2half2_rn(p[half * 2], p[half * 2 + 1]);
                    const uint32_t off = (uint32_t)(row0 + half * 8) * 128 + keyb;
                    *(uint32_t*)(sm + SP_OFF + sw128(off)) = *(const uint32_t*)&hp;
                }
            }
        }
        __syncthreads();

        if (kt <= 13) cp_wait<3>();
        else if (kt == 14) cp_wait<2>();
        else cp_wait<0>();
        __syncthreads();

        const uint32_t vBase = sV + buf * 16384;
#pragma unroll
        for (int ks = 0; ks < 4; ks++) {
            const uint32_t cb = ks * 32 + lc16;
            uint32_t af[2][4], bf[4][4];
#pragma unroll
            for (int mt = 0; mt < 2; mt++) {
                const uint32_t off = (uint32_t)(wm * 32 + mt * 16 + lr_) * 128 + cb;
                ldsm4(af[mt], sP + sw128(off));
            }
#pragma unroll
            for (int pr = 0; pr < 4; pr++) {
                const uint32_t off = (uint32_t)(wn * 64 + pr * 16 + lr_) * 128 + cb;
                ldsm4(bf[pr], vBase + sw128(off));
            }
#pragma unroll
            for (int mt = 0; mt < 2; mt++)
#pragma unroll
                for (int nt = 0; nt < 8; nt++)
                    mma16816(accO[mt][nt], af[mt],
                             bf[nt >> 1][nt & 1], bf[nt >> 1][(nt & 1) + 2]);
        }
        __syncthreads();
        if (kt + 2 <= 15) LOAD_V(kt + 2, buf);
    }

    // ---- rowsum reduction ----
#pragma unroll
    for (int mt = 0; mt < 2; mt++)
#pragma unroll
        for (int e = 0; e < 2; e++) {
            rs[mt][e] += __shfl_xor_sync(0xffffffffu, rs[mt][e], 1);
            rs[mt][e] += __shfl_xor_sync(0xffffffffu, rs[mt][e], 2);
        }
    if ((lane & 3) == 0) {
#pragma unroll
        for (int mt = 0; mt < 2; mt++)
#pragma unroll
            for (int e = 0; e < 2; e++)
                sRS[wn * 128 + wm * 32 + mt * 16 + (lane >> 2) + 8 * e] = rs[mt][e];
    }
    __syncthreads();

    // ---- normalize + write g_Acat rows for the output projection ----
    const int b = bh >> 4, h = bh & 15;
#pragma unroll
    for (int mt = 0; mt < 2; mt++) {
#pragma unroll
        for (int half = 0; half < 2; half++) {
            const int row = wm * 32 + mt * 16 + (lane >> 2) + 8 * half;
            const float inv = 1.0f / (sRS[row] + sRS[128 + row]);
            const int m = b * 1024 + (n0 + row);
            __half* ReRow = g_Acat + (size_t)m * K_EFF;
            __half* ImRow = g_Acat + (size_t)(m + 4096) * K_EFF;
#pragma unroll
            for (int nt = 0; nt < 8; nt++) {
                const int col = wn * 64 + nt * 8 + (lane & 3) * 2;
                const int d = col & 63;
                const int c = h * 64 + d;
                const float v0 = accO[mt][nt][half * 2] * inv;
                const float v1 = accO[mt][nt][half * 2 + 1] * inv;
                const __half2 hp = __floats2half2_rn(v0, v1);
                if (col < 64) {
                    // out_r: Re row col c ; Im row col 1024+c
                    *(uint32_t*)(ReRow + c) = *(const uint32_t*)&hp;
                    *(uint32_t*)(ImRow + 1024 + c) = *(const uint32_t*)&hp;
                } else {
                    // out_i: Re row col 1024+c = -oi ; Im row col c = oi
                    const __half2 hn = __hneg2(hp);
                    *(uint32_t*)(ReRow + 1024 + c) = *(const uint32_t*)&hn;
                    *(uint32_t*)(ImRow + c) = *(const uint32_t*)&hp;
                }
            }
        }
    }
}

// =================== launcher ===================
extern "C" void kernel_launch(void* const* d_in, const int* in_sizes, int n_in,
                              void* d_out, int out_size)
{
    const float* xr = (const float*)d_in[0];
    const float* xi = (const float*)d_in[1];
    const float* Wr = (const float*)d_in[2];
    const float* Wi = (const float*)d_in[3];
    const float* br = (const float*)d_in[4];
    const float* bi = (const float*)d_in[5];

    float* outR = (float*)d_out;
    float* outI = outR + (size_t)BATCH * SEQ * DIMV;

    cudaFuncSetAttribute(mma_gemm, cudaFuncAttributeMaxDynamicSharedMemorySize, SMEM_GEMM);
    cudaFuncSetAttribute(attn2_kernel, cudaFuncAttributeMaxDynamicSharedMemorySize, ATTN2_SMEM);

    conv_a_kernel<<<4096, 256>>>(xr, xi);
    conv_w_kernel<<<4096, 256>>>(Wr, Wi);

    // fused QKV projection; epilogue emits Qpack/Kpack fp16 + V fp32
    mma_gemm<<<dim3(3072 / BN, 8192 / BM), 256, SMEM_GEMM>>>(br, bi, nullptr, nullptr, 0);

    // V transpose-pack
    conv_v_kernel<<<4096, 256>>>();

    // tensor-core attention; epilogue writes g_Acat directly
    attn2_kernel<<<dim3(SEQ / 128, BH), 256, ATTN2_SMEM>>>();

    // output projection -> d_out
    mma_gemm<<<dim3(1024 / BN, 8192 / BM), 256, SMEM_GEMM>>>(br + 3 * DIMV, bi + 3 * DIMV,
                                                             outR, outI, 1);
}

// round 8
// speedup vs baseline: 6.6306x; 1.0297x over previous
#include <cuda_runtime.h>
#include <cuda_fp16.h>
#include <math.h>
#include <stdint.h>

#define DIMV   1024
#define HEADS  16
#define DH     64
#define BATCH  4
#define SEQ    1024
#define BH     (BATCH*HEADS)
#define K_EFF  2048
#define KBYTES (K_EFF*2)

// ---------------- device scratch ----------------
__device__ __half g_Acat[(size_t)8192*K_EFF];        // [real rows 0..4095 | imag rows 4096..8191]
__device__ __half g_Wcat[(size_t)4096*K_EFF];        // 4 layers x 1024 rows: [Wr Wi]
__device__ __half g_Qpack[(size_t)BH*SEQ*128];       // [bh][n][qr|qi]
__device__ __half g_Kpack[(size_t)BH*2*SEQ*128];     // [bh][variant][n]: v0=[kr ki], v1=[-ki kr]
__device__ __half g_Vp16[(size_t)BH*SEQ*128];        // [bh][n][vr|vi]  (n = key)

// ---------------- ptx helpers ----------------
__device__ __forceinline__ uint32_t smem_u32(const void* p) {
    uint32_t a;
    asm("{ .reg .u64 t; cvta.to.shared.u64 t, %1; cvt.u32.u64 %0, t; }" : "=r"(a) : "l"(p));
    return a;
}
__device__ __forceinline__ void cp16(uint32_t dst, const void* src) {
    asm volatile("cp.async.cg.shared.global [%0], [%1], 16;" :: "r"(dst), "l"(src) : "memory");
}
__device__ __forceinline__ void cp_commit() { asm volatile("cp.async.commit_group;" ::: "memory"); }
template<int N> __device__ __forceinline__ void cp_wait() {
    asm volatile("cp.async.wait_group %0;" :: "n"(N) : "memory");
}
__device__ __forceinline__ void ldsm4(uint32_t* r, uint32_t addr) {
    asm volatile("ldmatrix.sync.aligned.m8n8.x4.shared.b16 {%0,%1,%2,%3}, [%4];"
                 : "=r"(r[0]), "=r"(r[1]), "=r"(r[2]), "=r"(r[3]) : "r"(addr));
}
__device__ __forceinline__ void ldsm4t(uint32_t* r, uint32_t addr) {
    asm volatile("ldmatrix.sync.aligned.m8n8.x4.trans.shared.b16 {%0,%1,%2,%3}, [%4];"
                 : "=r"(r[0]), "=r"(r[1]), "=r"(r[2]), "=r"(r[3]) : "r"(addr));
}
__device__ __forceinline__ void mma16816(float* c, const uint32_t* a, uint32_t b0, uint32_t b1) {
    asm volatile(
        "mma.sync.aligned.m16n8k16.row.col.f32.f16.f16.f32 "
        "{%0,%1,%2,%3}, {%4,%5,%6,%7}, {%8,%9}, {%0,%1,%2,%3};"
        : "+f"(c[0]), "+f"(c[1]), "+f"(c[2]), "+f"(c[3])
        : "r"(a[0]), "r"(a[1]), "r"(a[2]), "r"(a[3]), "r"(b0), "r"(b1));
}
__device__ __forceinline__ uint32_t sw128(uint32_t off) { return off ^ ((off >> 3) & 0x70); }

// ---------------- fp16 store helpers ----------------
__device__ __forceinline__ void st4h(__half* p, const float* v) {
    __half2 a = __floats2half2_rn(v[0], v[1]);
    __half2 b = __floats2half2_rn(v[2], v[3]);
    uint2 u;
    u.x = *(const uint32_t*)&a;
    u.y = *(const uint32_t*)&b;
    *(uint2*)p = u;
}
__device__ __forceinline__ void st4hn(__half* p, const float* v) {
    __half2 a = __floats2half2_rn(-v[0], -v[1]);
    __half2 b = __floats2half2_rn(-v[2], -v[3]);
    uint2 u;
    u.x = *(const uint32_t*)&a;
    u.y = *(const uint32_t*)&b;
    *(uint2*)p = u;
}

// ---------------- merged conversion: A + W operands ----------------
// blocks 0..4095: A real row m: [xr, -xi], imag row m: [xi, xr]
// blocks 4096..8191: W row n: [Wr, Wi]
__global__ void conv_aw_kernel(const float* __restrict__ ar, const float* __restrict__ ai,
                               const float* __restrict__ Wr, const float* __restrict__ Wi)
{
    if (blockIdx.x < 4096) {
        const int idx = blockIdx.x * 256 + threadIdx.x;
        const int row = idx >> 8;
        const int c = (idx & 255) << 2;
        const size_t src = (size_t)row * 1024 + c;
        const float4 vr = *(const float4*)(ar + src);
        const float4 vi = *(const float4*)(ai + src);
        const float fr[4] = {vr.x, vr.y, vr.z, vr.w};
        const float fi[4] = {vi.x, vi.y, vi.z, vi.w};
        __half* Re = g_Acat + (size_t)row * K_EFF + c;
        __half* Im = g_Acat + (size_t)(row + 4096) * K_EFF + c;
        st4h (Re + 0,    fr);
        st4hn(Re + 1024, fi);
        st4h (Im + 0,    fi);
        st4h (Im + 1024, fr);
    } else {
        const int idx = (blockIdx.x - 4096) * 256 + threadIdx.x;
        const int row = idx >> 8;
        const int c = (idx & 255) << 2;
        const size_t src = (size_t)row * 1024 + c;
        const float4 vr = *(const float4*)(Wr + src);
        const float4 vi = *(const float4*)(Wi + src);
        const float fr[4] = {vr.x, vr.y, vr.z, vr.w};
        const float fi[4] = {vi.x, vi.y, vi.z, vi.w};
        __half* W = g_Wcat + (size_t)row * K_EFF + c;
        st4h(W + 0,    fr);
        st4h(W + 1024, fi);
    }
}

// ---------------- mma.sync projection GEMM ----------------
#define BM 128
#define BN 128
#define BK 64
#define NITER (K_EFF/BK)     // 32
#define A_ST  16384
#define ST_SZ 32768
#define SMEM_GEMM (3*ST_SZ)

__device__ __forceinline__ void load_stage(uint32_t sbase, int s, int kt, int tid,
                                           const __half* Ab, const __half* Bb)
{
    const char* aSrc = (const char*)Ab + (size_t)kt * (BK * 2);
    const char* bSrc = (const char*)Bb + (size_t)kt * (BK * 2);
    const uint32_t aDst = sbase + s * ST_SZ;
    const uint32_t bDst = aDst + A_ST;
#pragma unroll
    for (int i = 0; i < 4; i++) {
        const int q = tid + i * 256;
        const int row = q >> 3, cc = q & 7;
        const uint32_t sw = sw128(row * 128 + cc * 16);
        cp16(aDst + sw, aSrc + (size_t)row * KBYTES + cc * 16);
        cp16(bDst + sw, bSrc + (size_t)row * KBYTES + cc * 16);
    }
}

// epilogue: mode 0 writes Qpack/Kpack/Vp16 fp16; mode 1 writes final fp32 planes
__device__ __forceinline__ void epi_store(int mode, int gm, int gc,
                                          float v0, float v1,
                                          const float* biasR, const float* biasI,
                                          float* outR, float* outI)
{
    const int plane = gm >> 12;
    const int m = gm & 4095;
    const int b = m >> 10, n = m & 1023;
    const float* bias = plane ? biasI : biasR;
    const float f0 = v0 + bias[gc];
    const float f1 = v1 + bias[gc + 1];
    if (mode == 0) {
        const int layer = gc >> 10;
        const int cw = gc & 1023;
        const int h = cw >> 6, d = cw & 63;
        const int bh = b * HEADS + h;
        const __half2 hp = __floats2half2_rn(f0, f1);
        if (layer == 0) {
            __half* dst = g_Qpack + ((size_t)bh * SEQ + n) * 128 + plane * 64 + d;
            *(uint32_t*)dst = *(const uint32_t*)&hp;
        } else if (layer == 2) {
            __half* dst = g_Vp16 + ((size_t)bh * SEQ + n) * 128 + plane * 64 + d;
            *(uint32_t*)dst = *(const uint32_t*)&hp;
        } else {
            // v0 = [kr ki] : col plane*64+d
            __half* d0 = g_Kpack + (((size_t)bh * 2 + 0) * SEQ + n) * 128 + plane * 64 + d;
            *(uint32_t*)d0 = *(const uint32_t*)&hp;
            // v1 = [-ki kr] : kr (plane0) -> col 64+d ; ki (plane1) -> col d negated
            const __half2 hv = plane ? __hneg2(hp) : hp;
            __half* d1 = g_Kpack + (((size_t)bh * 2 + 1) * SEQ + n) * 128
                       + (plane ? 0 : 64) + d;
            *(uint32_t*)d1 = *(const uint32_t*)&hv;
        }
    } else {
        float* base = plane ? outI : outR;
        float2 v; v.x = f0; v.y = f1;
        *(float2*)(base + (size_t)m * 1024 + gc) = v;
    }
}

__global__ void __launch_bounds__(256, 2) mma_gemm(
    const float* __restrict__ biasR, const float* __restrict__ biasI,
    float* __restrict__ outR, float* __restrict__ outI, int mode)
{
    extern __shared__ char smem[];
    const uint32_t sbase = smem_u32(smem);
    const int tid = threadIdx.x;
    const int lane = tid & 31;
    const int wid = tid >> 5;
    const int wm = wid & 3;
    const int wn = wid >> 2;

    const __half* Ab = g_Acat + (size_t)blockIdx.y * BM * K_EFF;
    const __half* Bb = g_Wcat + (mode ? (size_t)3072 * K_EFF : 0)
                              + (size_t)blockIdx.x * BN * K_EFF;

    float acc[2][8][4];
#pragma unroll
    for (int mt = 0; mt < 2; mt++)
#pragma unroll
        for (int nt = 0; nt < 8; nt++)
#pragma unroll
            for (int r = 0; r < 4; r++) acc[mt][nt][r] = 0.f;

    load_stage(sbase, 0, 0, tid, Ab, Bb); cp_commit();
    load_stage(sbase, 1, 1, tid, Ab, Bb); cp_commit();

    const int lr_ = lane & 15;
    const int lc16 = (lane >> 4) * 16;

    for (int kt = 0; kt < NITER; kt++) {
        cp_wait<1>();
        __syncthreads();
        const int slot = kt % 3;
        const uint32_t aB = sbase + slot * ST_SZ;
        const uint32_t bB = aB + A_ST;
#pragma unroll
        for (int ks = 0; ks < 4; ks++) {
            const uint32_t cb = ks * 32 + lc16;
            uint32_t af[2][4], bf[4][4];
#pragma unroll
            for (int mt = 0; mt < 2; mt++) {
                const uint32_t off = (uint32_t)(wm * 32 + mt * 16 + lr_) * 128 + cb;
                ldsm4(af[mt], aB + sw128(off));
            }
#pragma unroll
            for (int pr = 0; pr < 4; pr++) {
                const uint32_t off = (uint32_t)(wn * 64 + pr * 16 + lr_) * 128 + cb;
                ldsm4(bf[pr], bB + sw128(off));
            }
#pragma unroll
            for (int mt = 0; mt < 2; mt++)
#pragma unroll
                for (int nt = 0; nt < 8; nt++)
                    mma16816(acc[mt][nt], af[mt],
                             bf[nt >> 1][nt & 1], bf[nt >> 1][(nt & 1) + 2]);
        }
        const int pk = kt + 2;
        if (pk < NITER) load_stage(sbase, pk % 3, pk, tid, Ab, Bb);
        cp_commit();
    }

    const int blockRow = blockIdx.y * BM;
    const int blockCol = blockIdx.x * BN;
#pragma unroll
    for (int mt = 0; mt < 2; mt++) {
        const int gr0 = blockRow + wm * 32 + mt * 16 + (lane >> 2);
#pragma unroll
        for (int nt = 0; nt < 8; nt++) {
            const int gc = blockCol + wn * 64 + nt * 8 + (lane & 3) * 2;
            epi_store(mode, gr0,     gc, acc[mt][nt][0], acc[mt][nt][1], biasR, biasI, outR, outI);
            epi_store(mode, gr0 + 8, gc, acc[mt][nt][2], acc[mt][nt][3], biasR, biasI, outR, outI);
        }
    }
}

// =================== tensor-core attention (fp16 single) ===================
// smem: Q 32KB | K 2x32KB | V 2x16KB | P 16KB | rowsum 1KB
#define SQ_OFF 0
#define SK_OFF 32768
#define SV_OFF (SK_OFF + 2*32768)
#define SP_OFF (SV_OFF + 2*16384)
#define SRS_OFF (SP_OFF + 16384)
#define ATTN2_SMEM (SRS_OFF + 1024)

__global__ void __launch_bounds__(256, 1) attn2_kernel()
{
    extern __shared__ char sm[];
    const uint32_t sb = smem_u32(sm);
    const uint32_t sQ = sb + SQ_OFF;
    const uint32_t sK = sb + SK_OFF;
    const uint32_t sV = sb + SV_OFF;
    const uint32_t sP = sb + SP_OFF;
    float* sRS = (float*)(sm + SRS_OFF);

    const int tid = threadIdx.x;
    const int lane = tid & 31;
    const int wid = tid >> 5;
    const int wm = wid & 3;
    const int wn = wid >> 2;
    const int bh = blockIdx.y;
    const int n0 = blockIdx.x * 128;

    const char* Qg  = (const char*)(g_Qpack + ((size_t)bh * SEQ + n0) * 128);
    const char* Kg0 = (const char*)(g_Kpack + ((size_t)bh * 2 + 0) * SEQ * 128);
    const char* Kg1 = (const char*)(g_Kpack + ((size_t)bh * 2 + 1) * SEQ * 128);
    const char* Vg  = (const char*)(g_Vp16 + (size_t)bh * SEQ * 128);

    // Q: 128 rows x 256B (two 16KB chunks)
#pragma unroll
    for (int i = 0; i < 8; i++) {
        const int q = tid + i * 256;
        const int row = q >> 4, cc = q & 15;
        const int ch = cc >> 3, w = cc & 7;
        cp16(sQ + ch * 16384 + sw128(row * 128 + w * 16),
             Qg + (size_t)row * 256 + cc * 16);
    }
    cp_commit();

#define LOAD_K(ktile, buf) do { \
    _Pragma("unroll") \
    for (int i = 0; i < 8; i++) { \
        const int q = tid + i * 256; \
        const int row = q >> 4, cc = q & 15; \
        const int ch = cc >> 3, w = cc & 7; \
        const char* src = (row < 64) \
            ? Kg0 + (size_t)((ktile) * 64 + row) * 256 + cc * 16 \
            : Kg1 + (size_t)((ktile) * 64 + row - 64) * 256 + cc * 16; \
        cp16(sK + (buf) * 32768 + ch * 16384 + sw128(row * 128 + w * 16), src); \
    } \
    cp_commit(); } while (0)

// V tile: 64 key rows x 256B -> two 8KB chunks (cols 0-127 / 128-255)
#define LOAD_V(ktile, buf) do { \
    _Pragma("unroll") \
    for (int i = 0; i < 4; i++) { \
        const int q = tid + i * 256; \
        const int row = q >> 4, cc = q & 15; \
        const int ch = cc >> 3, w = cc & 7; \
        cp16(sV + (buf) * 16384 + ch * 8192 + sw128(row * 128 + w * 16), \
             Vg + (size_t)((ktile) * 64 + row) * 256 + cc * 16); \
    } \
    cp_commit(); } while (0)

    LOAD_K(0, 0);
    LOAD_V(0, 0);
    LOAD_K(1, 1);
    LOAD_V(1, 1);

    float accO[2][8][4];
#pragma unroll
    for (int mt = 0; mt < 2; mt++)
#pragma unroll
        for (int nt = 0; nt < 8; nt++)
#pragma unroll
            for (int e = 0; e < 4; e++) accO[mt][nt][e] = 0.f;
    float rs[2][2] = {{0.f, 0.f}, {0.f, 0.f}};

    const int lr_ = lane & 15;
    const int lc16 = (lane >> 4) * 16;
    const int lr8 = lane & 7;
    const int lgrp = lane >> 3;

    for (int kt = 0; kt < 16; kt++) {
        const int buf = kt & 1;
        if (kt <= 14) cp_wait<3>(); else cp_wait<1>();
        __syncthreads();

        float accS[2][8][4];
#pragma unroll
        for (int mt = 0; mt < 2; mt++)
#pragma unroll
            for (int nt = 0; nt < 8; nt++)
#pragma unroll
                for (int e = 0; e < 4; e++) accS[mt][nt][e] = 0.f;

        const uint32_t kBase = sK + buf * 32768;
#pragma unroll
        for (int ks = 0; ks < 8; ks++) {
            const uint32_t cbf = ks * 32 + lc16;
            const uint32_t ch = cbf >> 7;
            const uint32_t w = cbf & 127;
            uint32_t af[2][4], bf[4][4];
#pragma unroll
            for (int mt = 0; mt < 2; mt++) {
                const uint32_t off = (uint32_t)(wm * 32 + mt * 16 + lr_) * 128 + w;
                ldsm4(af[mt], sQ + ch * 16384 + sw128(off));
            }
#pragma unroll
            for (int pr = 0; pr < 4; pr++) {
                const int rbase = (pr < 2) ? (wn * 32 + pr * 16)
                                           : (64 + wn * 32 + (pr - 2) * 16);
                const uint32_t off = (uint32_t)(rbase + lr_) * 128 + w;
                ldsm4(bf[pr], kBase + ch * 16384 + sw128(off));
            }
#pragma unroll
            for (int mt = 0; mt < 2; mt++)
#pragma unroll
                for (int nt = 0; nt < 8; nt++)
                    mma16816(accS[mt][nt], af[mt],
                             bf[nt >> 1][nt & 1], bf[nt >> 1][(nt & 1) + 2]);
        }
        __syncthreads();
        if (kt + 2 <= 15) LOAD_K(kt + 2, buf);

        // ---- softmax -> P (fp16) ----
#pragma unroll
        for (int mt = 0; mt < 2; mt++) {
#pragma unroll
            for (int nt = 0; nt < 4; nt++) {
                float p[4];
#pragma unroll
                for (int e = 0; e < 4; e++) {
                    const float srv = accS[mt][nt][e];
                    const float siv = accS[mt][nt + 4][e];
                    p[e] = __expf(sqrtf(srv * srv + siv * siv) * 0.125f);
                }
                rs[mt][0] += p[0] + p[1];
                rs[mt][1] += p[2] + p[3];
                const int keyb = (wn * 32 + nt * 8 + (lane & 3) * 2) * 2;
                const int row0 = wm * 32 + mt * 16 + (lane >> 2);
#pragma unroll
                for (int half = 0; half < 2; half++) {
                    const __half2 hp = __floats2half2_rn(p[half * 2], p[half * 2 + 1]);
                    const uint32_t off = (uint32_t)(row0 + half * 8) * 128 + keyb;
                    *(uint32_t*)(sm + SP_OFF + sw128(off)) = *(const uint32_t*)&hp;
                }
            }
        }
        __syncthreads();

        if (kt <= 13) cp_wait<3>();
        else if (kt == 14) cp_wait<2>();
        else cp_wait<0>();
        __syncthreads();

        // ---- PV: accO += P[128x64keys] @ V'[key][128 cols] via ldsm.trans ----
        const uint32_t vBase = sV + buf * 16384;
#pragma unroll
        for (int ks = 0; ks < 4; ks++) {
            const uint32_t cb = ks * 32 + lc16;
            uint32_t af[2][4];
#pragma unroll
            for (int mt = 0; mt < 2; mt++) {
                const uint32_t off = (uint32_t)(wm * 32 + mt * 16 + lr_) * 128 + cb;
                ldsm4(af[mt], sP + sw128(off));
            }
#pragma unroll
            for (int pr = 0; pr < 4; pr++) {
                const uint32_t colByte = (uint32_t)(wn * 128 + pr * 32 + ((lgrp >> 1) << 4));
                const uint32_t vrow = (uint32_t)(ks * 16 + ((lgrp & 1) << 3) + lr8);
                uint32_t bt[4];
                ldsm4t(bt, vBase + (colByte >> 7) * 8192 + sw128(vrow * 128 + (colByte & 127)));
#pragma unroll
                for (int mt = 0; mt < 2; mt++) {
                    mma16816(accO[mt][2 * pr],     af[mt], bt[0], bt[1]);
                    mma16816(accO[mt][2 * pr + 1], af[mt], bt[2], bt[3]);
                }
            }
        }
        __syncthreads();
        if (kt + 2 <= 15) LOAD_V(kt + 2, buf);
    }

    // ---- rowsum reduction ----
#pragma unroll
    for (int mt = 0; mt < 2; mt++)
#pragma unroll
        for (int e = 0; e < 2; e++) {
            rs[mt][e] += __shfl_xor_sync(0xffffffffu, rs[mt][e], 1);
            rs[mt][e] += __shfl_xor_sync(0xffffffffu, rs[mt][e], 2);
        }
    if ((lane & 3) == 0) {
#pragma unroll
        for (int mt = 0; mt < 2; mt++)
#pragma unroll
            for (int e = 0; e < 2; e++)
                sRS[wn * 128 + wm * 32 + mt * 16 + (lane >> 2) + 8 * e] = rs[mt][e];
    }
    __syncthreads();

    // ---- normalize + write g_Acat rows for the output projection ----
    const int b = bh >> 4, h = bh & 15;
#pragma unroll
    for (int mt = 0; mt < 2; mt++) {
#pragma unroll
        for (int half = 0; half < 2; half++) {
            const int row = wm * 32 + mt * 16 + (lane >> 2) + 8 * half;
            const float inv = 1.0f / (sRS[row] + sRS[128 + row]);
            const int m = b * 1024 + (n0 + row);
            __half* ReRow = g_Acat + (size_t)m * K_EFF;
            __half* ImRow = g_Acat + (size_t)(m + 4096) * K_EFF;
#pragma unroll
            for (int nt = 0; nt < 8; nt++) {
                const int col = wn * 64 + nt * 8 + (lane & 3) * 2;
                const int d = col & 63;
                const int c = h * 64 + d;
                const float v0 = accO[mt][nt][half * 2] * inv;
                const float v1 = accO[mt][nt][half * 2 + 1] * inv;
                const __half2 hp = __floats2half2_rn(v0, v1);
                if (col < 64) {
                    *(uint32_t*)(ReRow + c) = *(const uint32_t*)&hp;
                    *(uint32_t*)(ImRow + 1024 + c) = *(const uint32_t*)&hp;
                } else {
                    const __half2 hn = __hneg2(hp);
                    *(uint32_t*)(ReRow + 1024 + c) = *(const uint32_t*)&hn;
                    *(uint32_t*)(ImRow + c) = *(const uint32_t*)&hp;
                }
            }
        }
    }
}

// =================== launcher ===================
extern "C" void kernel_launch(void* const* d_in, const int* in_sizes, int n_in,
                              void* d_out, int out_size)
{
    const float* xr = (const float*)d_in[0];
    const float* xi = (const float*)d_in[1];
    const float* Wr = (const float*)d_in[2];
    const float* Wi = (const float*)d_in[3];
    const float* br = (const float*)d_in[4];
    const float* bi = (const float*)d_in[5];

    float* outR = (float*)d_out;
    float* outI = outR + (size_t)BATCH * SEQ * DIMV;

    cudaFuncSetAttribute(mma_gemm, cudaFuncAttributeMaxDynamicSharedMemorySize, SMEM_GEMM);
    cudaFuncSetAttribute(attn2_kernel, cudaFuncAttributeMaxDynamicSharedMemorySize, ATTN2_SMEM);

    // build fp16 A and W operands (merged)
    conv_aw_kernel<<<8192, 256>>>(xr, xi, Wr, Wi);

    // fused QKV projection; epilogue emits Qpack/Kpack/Vp16 fp16 directly
    mma_gemm<<<dim3(3072 / BN, 8192 / BM), 256, SMEM_GEMM>>>(br, bi, nullptr, nullptr, 0);

    // tensor-core attention; epilogue writes g_Acat directly
    attn2_kernel<<<dim3(SEQ / 128, BH), 256, ATTN2_SMEM>>>();

    // output projection -> d_out
    mma_gemm<<<dim3(1024 / BN, 8192 / BM), 256, SMEM_GEMM>>>(br + 3 * DIMV, bi + 3 * DIMV,
                                                             outR, outI, 1);
}